// round 13
// baseline (speedup 1.0000x reference)
#include <cuda_runtime.h>
#include <cuda_bf16.h>
#include <cstdint>

// ---------------------------------------------------------------------------
// GraphSAGE, mma.sync bf16 hi/lo (3-product fp32-accurate).
// layer0_k: weight pre-split fused (8 converter CTAs + acquire flag); 4 GEMM
//   segments INTERLEAVED at bid granularity (every 8 bids: 3x mean5,
//   3x F1self, 1x F0neigh, 1x F0self) so each wave mixes gather-bound and
//   MMA-bound CTAs. gemm_body = 256 thr, M64 x N128, K=256 in 4 chunks,
//   2 CTAs/SM.
// l1fc_k: 256 thr, 2 CTAs/SM; stage1 M64 x N256 layer-1 (k32 chunks), row
//   L2-norm, stage2 FC — all fused.
// ---------------------------------------------------------------------------

#define B_ROOT 16384
#define R1     49152
#define RSA    72            // k64 tile row stride (bf16 elems)
#define RSC    40            // k32 tile row stride (bf16 elems)
#define RSH    264           // h row stride

// layer0 smem (bytes)
#define GA(b)  ((b) * 18432)                 // A: hi +0, lo +9216
#define GW(b)  (36864 + (b) * 36864)         // W: hi +0, lo +18432
#define G_SMEM 110592
// l1fc smem (bytes)
#define C_ASH  0                              // self A hi   [64][40]
#define C_ASL  5120
#define C_ANH  10240
#define C_ANL  15360
#define C_W(b) (20480 + (b) * 40960)          // W buf: hi +0 (20480), lo +20480
#define C_HH   0                              // stage2: h hi [64][264]
#define C_HL   33792
#define C_FC   67584                          // fc buf: hi +0 (18432), lo +18432
#define C_SS   104448                         // float ss[64]
#define L_SMEM 104704

// ---------------- scratch ----------------------------------------------------
__device__ float g_F0[B_ROOT * 256];
__device__ float g_F1[R1 * 256];
__device__ __nv_bfloat16 g_whi[5 * 32768];
__device__ __nv_bfloat16 g_wlo[5 * 32768];
__device__ unsigned g_wflag;

// ---------------- helpers ----------------------------------------------------
__device__ __forceinline__ uint32_t smem_u32(const void* p) {
    uint32_t a;
    asm("{ .reg .u64 t; cvta.to.shared.u64 t, %1; cvt.u32.u64 %0, t; }"
        : "=r"(a) : "l"(p));
    return a;
}
__device__ __forceinline__ void split2(float a, float b, uint32_t& h, uint32_t& l) {
    __nv_bfloat16 ah = __float2bfloat16_rn(a), bh = __float2bfloat16_rn(b);
    __nv_bfloat16 al = __float2bfloat16_rn(a - __bfloat162float(ah));
    __nv_bfloat16 bl = __float2bfloat16_rn(b - __bfloat162float(bh));
    __nv_bfloat162 ph = __halves2bfloat162(ah, bh);
    __nv_bfloat162 pl = __halves2bfloat162(al, bl);
    h = *reinterpret_cast<uint32_t*>(&ph);
    l = *reinterpret_cast<uint32_t*>(&pl);
}
__device__ __forceinline__ void split8(const float* v, uint4& h4, uint4& l4) {
    uint32_t h[4], l[4];
#pragma unroll
    for (int i = 0; i < 4; ++i) split2(v[2 * i], v[2 * i + 1], h[i], l[i]);
    h4 = make_uint4(h[0], h[1], h[2], h[3]);
    l4 = make_uint4(l[0], l[1], l[2], l[3]);
}
__device__ __forceinline__ void mma16816(float* d, const uint32_t* a,
                                         uint32_t b0, uint32_t b1) {
    asm volatile(
        "mma.sync.aligned.m16n8k16.row.col.f32.bf16.bf16.f32 "
        "{%0,%1,%2,%3}, {%4,%5,%6,%7}, {%8,%9}, {%0,%1,%2,%3};"
        : "+f"(d[0]), "+f"(d[1]), "+f"(d[2]), "+f"(d[3])
        : "r"(a[0]), "r"(a[1]), "r"(a[2]), "r"(a[3]), "r"(b0), "r"(b1));
}
__device__ __forceinline__ void ldmx4(uint32_t* r, uint32_t a) {
    asm volatile("ldmatrix.sync.aligned.m8n8.x4.shared.b16 {%0,%1,%2,%3}, [%4];"
                 : "=r"(r[0]), "=r"(r[1]), "=r"(r[2]), "=r"(r[3]) : "r"(a));
}
__device__ __forceinline__ void cp16(uint32_t dst, const void* src) {
    asm volatile("cp.async.cg.shared.global [%0], [%1], 16;" :: "r"(dst), "l"(src));
}
#define CP_COMMIT() asm volatile("cp.async.commit_group;" ::: "memory")
#define CP_WAIT0()  asm volatile("cp.async.wait_group 0;"  ::: "memory")

// ---------------- layer-0 GEMM body (unchanged, proven) ------------------------
template <int GATHER, int KF>
__device__ __forceinline__ void
gemm_body(char* smem, const float* __restrict__ A, const int* __restrict__ idx,
          const __nv_bfloat16* __restrict__ w_hi, const __nv_bfloat16* __restrict__ w_lo,
          const float* __restrict__ bias,
          float* __restrict__ C, int ldc, int col_off, int m0)
{
    const uint32_t sb = smem_u32(smem);
    const int tid = threadIdx.x, lane = tid & 31, wid = tid >> 5;
    const int wm = wid >> 2, wn = wid & 3;
    const int lr = lane >> 2, lc = (lane & 3) * 2;
    const int g  = lane >> 3, lm = lane & 7;
    const int aro = ((g & 1) << 3) + lm, aco = (g >> 1) << 3;
    const int bro = ((g >> 1) << 3) + lm, bco = (g & 1) << 3;
    const int r  = tid >> 2, cq = (tid & 3) * 16;

    auto ISSUE_W = [&](int ch, int buf) {
        const int kb = ch * 64;
#pragma unroll
        for (int i = 0; i < 8; ++i) {
            int o = tid + i * 256;
            int plane = o >> 10, ix = o & 1023;
            int row = ix >> 3, c8 = (ix & 7) * 8;
            const __nv_bfloat16* src =
                (plane ? w_lo : w_hi) + (size_t)row * 256 + kb + c8;
            cp16(sb + GW(buf) + (plane ? 18432 : 0)
                 + (uint32_t)(row * RSA + c8) * 2, src);
        }
    };

    int rows[KF];
    if (GATHER == 0)      rows[0] = idx[m0 + r];
    else {
#pragma unroll
        for (int j = 0; j < KF; ++j) rows[j] = idx[(size_t)(m0 + r) * KF + j];
    }

    float v[16];
    auto PREF = [&](int ch) {
        const int kb = ch * 64;
        if (GATHER == 0) {
            const float4* p = (const float4*)(A + (size_t)rows[0] * 256 + kb + cq);
            float4 t0 = __ldg(p), t1 = __ldg(p + 1), t2 = __ldg(p + 2), t3 = __ldg(p + 3);
            v[0]  = t0.x; v[1]  = t0.y; v[2]  = t0.z; v[3]  = t0.w;
            v[4]  = t1.x; v[5]  = t1.y; v[6]  = t1.z; v[7]  = t1.w;
            v[8]  = t2.x; v[9]  = t2.y; v[10] = t2.z; v[11] = t2.w;
            v[12] = t3.x; v[13] = t3.y; v[14] = t3.z; v[15] = t3.w;
        } else {
#pragma unroll
            for (int i = 0; i < 16; ++i) v[i] = 0.f;
#pragma unroll
            for (int h = 0; h < 2; ++h) {
                float4 t[2 * KF];
#pragma unroll
                for (int j = 0; j < KF; ++j) {
                    const float4* p = (const float4*)(A + (size_t)rows[j] * 256
                                                      + kb + cq + h * 8);
                    t[j * 2]     = __ldg(p);
                    t[j * 2 + 1] = __ldg(p + 1);
                }
#pragma unroll
                for (int j = 0; j < KF; ++j)
#pragma unroll
                    for (int q = 0; q < 2; ++q) {
                        const float4 f = t[j * 2 + q];
                        const int o = h * 8 + q * 4;
                        v[o + 0] += f.x; v[o + 1] += f.y;
                        v[o + 2] += f.z; v[o + 3] += f.w;
                    }
            }
        }
    };
    auto STORE = [&](int buf) {
        const float s = 1.0f / (float)KF;
        float w[16];
#pragma unroll
        for (int i = 0; i < 16; ++i) w[i] = v[i] * s;
        uint4 h0, l0, h1, l1;
        split8(w, h0, l0);
        split8(w + 8, h1, l1);
        char* base = smem + GA(buf) + (size_t)(r * RSA + cq) * 2;
        *(uint4*)(base)              = h0;
        *(uint4*)(base + 16)         = h1;
        *(uint4*)(base + 9216)       = l0;
        *(uint4*)(base + 9216 + 16)  = l1;
    };

    float d[2][4][4];
#pragma unroll
    for (int i = 0; i < 2; ++i)
#pragma unroll
        for (int j = 0; j < 4; ++j)
#pragma unroll
            for (int k = 0; k < 4; ++k) d[i][j][k] = 0.f;

    ISSUE_W(0, 0);
    CP_COMMIT();
    PREF(0);
    STORE(0);
    CP_WAIT0();
    __syncthreads();

#pragma unroll
    for (int ch = 0; ch < 4; ++ch) {
        const int cb = ch & 1, nb = cb ^ 1;
        if (ch < 3) {
            ISSUE_W(ch + 1, nb);
            CP_COMMIT();
            PREF(ch + 1);
        }
        const uint32_t aH = sb + GA(cb), aL = aH + 9216;
        const uint32_t wH = sb + GW(cb), wL = wH + 18432;
#pragma unroll
        for (int ks = 0; ks < 4; ++ks) {
            uint32_t ah[2][4], al[2][4];
#pragma unroll
            for (int mi = 0; mi < 2; ++mi) {
                uint32_t ad = (uint32_t)((wm * 32 + mi * 16 + aro) * RSA
                                         + ks * 16 + aco) * 2;
                ldmx4(ah[mi], aH + ad);
                ldmx4(al[mi], aL + ad);
            }
            uint32_t bh[4][2], bl[4][2];
#pragma unroll
            for (int nip = 0; nip < 2; ++nip) {
                uint32_t bd = (uint32_t)((wn * 32 + nip * 16 + bro) * RSA
                                         + ks * 16 + bco) * 2;
                uint32_t t4[4];
                ldmx4(t4, wH + bd);
                bh[2 * nip][0] = t4[0]; bh[2 * nip][1] = t4[1];
                bh[2 * nip + 1][0] = t4[2]; bh[2 * nip + 1][1] = t4[3];
                ldmx4(t4, wL + bd);
                bl[2 * nip][0] = t4[0]; bl[2 * nip][1] = t4[1];
                bl[2 * nip + 1][0] = t4[2]; bl[2 * nip + 1][1] = t4[3];
            }
#pragma unroll
            for (int ni = 0; ni < 4; ++ni)
#pragma unroll
                for (int mi = 0; mi < 2; ++mi) {
                    mma16816(d[mi][ni], ah[mi], bh[ni][0], bh[ni][1]);
                    mma16816(d[mi][ni], ah[mi], bl[ni][0], bl[ni][1]);
                    mma16816(d[mi][ni], al[mi], bh[ni][0], bh[ni][1]);
                }
        }
        if (ch < 3) {
            STORE(nb);
            CP_WAIT0();
        }
        __syncthreads();
    }

#pragma unroll
    for (int mi = 0; mi < 2; ++mi) {
        const int row = m0 + wm * 32 + mi * 16 + lr;
#pragma unroll
        for (int ni = 0; ni < 4; ++ni) {
            const int col = wn * 32 + ni * 8 + lc;
            const float b0 = __ldg(&bias[col]), b1 = __ldg(&bias[col + 1]);
            *(float2*)(C + (size_t)row * ldc + col_off + col) =
                make_float2(fmaxf(d[mi][ni][0] + b0, 0.f),
                            fmaxf(d[mi][ni][1] + b1, 0.f));
            *(float2*)(C + (size_t)(row + 8) * ldc + col_off + col) =
                make_float2(fmaxf(d[mi][ni][2] + b0, 0.f),
                            fmaxf(d[mi][ni][3] + b1, 0.f));
        }
    }
}

// ---------------- layer 0: fused weight-split + INTERLEAVED segments -------------
// Every 8 consecutive bids: subs 0-2 -> mean5 (F1 neigh), subs 3-5 -> F1 self,
// sub 6 -> F0 neigh (mean3), sub 7 -> F0 self. grp = bid>>3 in [0,256).
__global__ void __launch_bounds__(256, 2)
layer0_k(const float* __restrict__ emb,
         const int* __restrict__ nodeids, const int* __restrict__ neigh1,
         const int* __restrict__ neigh2,
         const float* __restrict__ ws0, const float* __restrict__ wn0,
         const float* __restrict__ ws1, const float* __restrict__ wn1,
         const float* __restrict__ fcw,
         __nv_bfloat16* __restrict__ whi_o, __nv_bfloat16* __restrict__ wlo_o,
         const __nv_bfloat16* __restrict__ whi, const __nv_bfloat16* __restrict__ wlo,
         const float* __restrict__ bs0, const float* __restrict__ bn0,
         float* __restrict__ F0, float* __restrict__ F1)
{
    extern __shared__ char smem[];
    const int bid = blockIdx.x;
    const int tid = threadIdx.x;

    if (bid < 8) {
        const float* src[5] = {ws0, wn0, ws1, wn1, fcw};
#pragma unroll
        for (int i = 0; i < 20; ++i) {
            int idx4 = bid * 5120 + i * 256 + tid;
            int base = idx4 * 4;
            float4 f = __ldg((const float4*)(src[base >> 15] + (base & 32767)));
            uint32_t h0, l0, h1, l1;
            split2(f.x, f.y, h0, l0);
            split2(f.z, f.w, h1, l1);
            *(uint2*)(whi_o + base) = make_uint2(h0, h1);
            *(uint2*)(wlo_o + base) = make_uint2(l0, l1);
        }
        __syncthreads();
        if (tid == 0) {
            unsigned old;
            asm volatile("atom.add.release.gpu.u32 %0, [%1], 1;"
                         : "=r"(old) : "l"(&g_wflag) : "memory");
        }
    }
    if (tid == 0) {
        unsigned val;
        do {
            asm volatile("ld.acquire.gpu.u32 %0, [%1];"
                         : "=r"(val) : "l"(&g_wflag) : "memory");
            if (val >= 8u) break;
            __nanosleep(64);
        } while (true);
    }
    __syncthreads();

    const int grp = bid >> 3, sub = bid & 7;
    if (sub < 3) {
        gemm_body<1, 5>(smem, emb, neigh2, whi + 32768, wlo + 32768, bn0,
                        F1, 256, 128, (grp * 3 + sub) * 64);
    } else if (sub < 6) {
        gemm_body<0, 1>(smem, emb, neigh1, whi, wlo, bs0,
                        F1, 256, 0, (grp * 3 + (sub - 3)) * 64);
    } else if (sub == 6) {
        gemm_body<1, 3>(smem, emb, neigh1, whi + 32768, wlo + 32768, bn0,
                        F0, 256, 128, grp * 64);
    } else {
        gemm_body<0, 1>(smem, emb, nodeids, whi, wlo, bs0,
                        F0, 256, 0, grp * 64);
    }
}

// ---------------- fused layer1 + L2-norm + FC, 256 thr, 2 CTAs/SM ----------------
__global__ void __launch_bounds__(256, 2)
l1fc_k(const float* __restrict__ F0, const float* __restrict__ F1,
       const __nv_bfloat16* __restrict__ w1_hi, const __nv_bfloat16* __restrict__ w1_lo,
       const float* __restrict__ bS, const float* __restrict__ bN,
       const __nv_bfloat16* __restrict__ fc_hi, const __nv_bfloat16* __restrict__ fc_lo,
       const float* __restrict__ fcb, float* __restrict__ out)
{
    extern __shared__ char smem[];
    const uint32_t sb = smem_u32(smem);
    const int tid = threadIdx.x, lane = tid & 31, wid = tid >> 5;
    const int wm = wid >> 2, wn = wid & 3;          // stage1: 2m x 4n, warp 32x64
    const int lr = lane >> 2, lc = (lane & 3) * 2;
    const int g  = lane >> 3, lm = lane & 7;
    const int aro = ((g & 1) << 3) + lm, aco = (g >> 1) << 3;
    const int bro = ((g >> 1) << 3) + lm, bco = (g & 1) << 3;
    const int m0 = blockIdx.x * 64;

    if (blockIdx.x == 0 && tid == 0) {
        asm volatile("st.relaxed.gpu.u32 [%0], 0;" :: "l"(&g_wflag) : "memory");
    }

    const bool isSelf = tid < 128;
    const int lt = tid & 127;
    const int r = lt >> 1, cq = (lt & 1) * 16;

    auto ISSUE_W = [&](int ch, int buf) {
        const int kb = ch * 32;
#pragma unroll
        for (int i = 0; i < 8; ++i) {
            int o = tid + i * 256;
            int plane = o >> 10, ix = o & 1023;
            int row = ix >> 2, c8 = (ix & 3) * 8;
            const __nv_bfloat16* src =
                (plane ? w1_lo : w1_hi) + (size_t)row * 256 + kb + c8;
            cp16(sb + C_W(buf) + (plane ? 20480 : 0)
                 + (uint32_t)(row * RSC + c8) * 2, src);
        }
    };

    float v[16];
    auto PREF = [&](int ch) {
        const int kb = ch * 32;
        if (isSelf) {
            const float4* p = (const float4*)(F0 + (size_t)(m0 + r) * 256 + kb + cq);
            float4 t0 = __ldg(p), t1 = __ldg(p + 1), t2 = __ldg(p + 2), t3 = __ldg(p + 3);
            v[0]  = t0.x; v[1]  = t0.y; v[2]  = t0.z; v[3]  = t0.w;
            v[4]  = t1.x; v[5]  = t1.y; v[6]  = t1.z; v[7]  = t1.w;
            v[8]  = t2.x; v[9]  = t2.y; v[10] = t2.z; v[11] = t2.w;
            v[12] = t3.x; v[13] = t3.y; v[14] = t3.z; v[15] = t3.w;
        } else {
            float4 t[12];
#pragma unroll
            for (int j = 0; j < 3; ++j) {
                const float4* p = (const float4*)(F1
                    + (size_t)((m0 + r) * 3 + j) * 256 + kb + cq);
#pragma unroll
                for (int q = 0; q < 4; ++q) t[j * 4 + q] = __ldg(p + q);
            }
#pragma unroll
            for (int i = 0; i < 16; ++i) v[i] = 0.f;
#pragma unroll
            for (int j = 0; j < 3; ++j)
#pragma unroll
                for (int q = 0; q < 4; ++q) {
                    const float4 f = t[j * 4 + q];
                    v[q * 4 + 0] += f.x; v[q * 4 + 1] += f.y;
                    v[q * 4 + 2] += f.z; v[q * 4 + 3] += f.w;
                }
#pragma unroll
            for (int i = 0; i < 16; ++i) v[i] *= (1.0f / 3.0f);
        }
    };
    auto STORE = [&]() {
        uint4 h0, l0, h1, l1;
        split8(v, h0, l0);
        split8(v + 8, h1, l1);
        char* base = smem + (isSelf ? C_ASH : C_ANH) + (size_t)(r * RSC + cq) * 2;
        *(uint4*)(base)             = h0;
        *(uint4*)(base + 16)        = h1;
        *(uint4*)(base + 5120)      = l0;
        *(uint4*)(base + 5120 + 16) = l1;
    };

    float d[2][8][4];
#pragma unroll
    for (int i = 0; i < 2; ++i)
#pragma unroll
        for (int j = 0; j < 8; ++j)
#pragma unroll
            for (int k = 0; k < 4; ++k) d[i][j][k] = 0.f;

    ISSUE_W(0, 0);
    CP_COMMIT();
    PREF(0);
    STORE();
    CP_WAIT0();
    __syncthreads();

#pragma unroll
    for (int ch = 0; ch < 8; ++ch) {
        const int cb = ch & 1, nb = cb ^ 1;
        if (ch < 7) {
            ISSUE_W(ch + 1, nb);
            CP_COMMIT();
            PREF(ch + 1);
        }
        const uint32_t aH = sb + (wn < 2 ? C_ASH : C_ANH);
        const uint32_t aL = aH + 5120;
        const uint32_t wH = sb + C_W(cb), wL = wH + 20480;
#pragma unroll
        for (int ks = 0; ks < 2; ++ks) {
            uint32_t ah[2][4], al[2][4];
#pragma unroll
            for (int mi = 0; mi < 2; ++mi) {
                uint32_t ad = (uint32_t)((wm * 32 + mi * 16 + aro) * RSC
                                         + ks * 16 + aco) * 2;
                ldmx4(ah[mi], aH + ad);
                ldmx4(al[mi], aL + ad);
            }
#pragma unroll
            for (int nip = 0; nip < 4; ++nip) {
                uint32_t bd = (uint32_t)((wn * 64 + nip * 16 + bro) * RSC
                                         + ks * 16 + bco) * 2;
                uint32_t th[4], tl[4];
                ldmx4(th, wH + bd);
                ldmx4(tl, wL + bd);
#pragma unroll
                for (int sub = 0; sub < 2; ++sub) {
                    const int ni = 2 * nip + sub;
#pragma unroll
                    for (int mi = 0; mi < 2; ++mi) {
                        mma16816(d[mi][ni], ah[mi], th[2 * sub], th[2 * sub + 1]);
                        mma16816(d[mi][ni], ah[mi], tl[2 * sub], tl[2 * sub + 1]);
                        mma16816(d[mi][ni], al[mi], th[2 * sub], th[2 * sub + 1]);
                    }
                }
            }
        }
        __syncthreads();
        if (ch < 7) {
            STORE();
            CP_WAIT0();
            __syncthreads();
        }
    }

    auto ISSUE_FC = [&](int ch) {
        const int kb = ch * 64;
#pragma unroll
        for (int i = 0; i < 8; ++i) {
            int o = tid + i * 256;
            int plane = o >> 10, ix = o & 1023;
            int row = ix >> 3, c8 = (ix & 7) * 8;
            const __nv_bfloat16* src = (plane ? fc_lo : fc_hi)
                                     + (size_t)row * 256 + kb + c8;
            cp16(sb + C_FC + (plane ? 18432 : 0)
                 + (uint32_t)(row * RSA + c8) * 2, src);
        }
    };
    ISSUE_FC(0);
    CP_COMMIT();

    float* ss = (float*)(smem + C_SS);
    if (tid < 64) ss[tid] = 0.f;
    __syncthreads();

#pragma unroll
    for (int mi = 0; mi < 2; ++mi) {
        const int r0 = wm * 32 + mi * 16 + lr;
        float s0 = 0.f, s1 = 0.f;
#pragma unroll
        for (int ni = 0; ni < 8; ++ni) {
            const int col = wn * 64 + ni * 8 + lc;
            const float b0 = (col < 128) ? bS[col] : bN[col - 128];
            const float b1 = (col + 1 < 128) ? bS[col + 1] : bN[col - 127];
            d[mi][ni][0] = fmaxf(d[mi][ni][0] + b0, 0.f);
            d[mi][ni][1] = fmaxf(d[mi][ni][1] + b1, 0.f);
            d[mi][ni][2] = fmaxf(d[mi][ni][2] + b0, 0.f);
            d[mi][ni][3] = fmaxf(d[mi][ni][3] + b1, 0.f);
            s0 += d[mi][ni][0] * d[mi][ni][0] + d[mi][ni][1] * d[mi][ni][1];
            s1 += d[mi][ni][2] * d[mi][ni][2] + d[mi][ni][3] * d[mi][ni][3];
        }
        s0 += __shfl_xor_sync(0xffffffffu, s0, 1);
        s0 += __shfl_xor_sync(0xffffffffu, s0, 2);
        s1 += __shfl_xor_sync(0xffffffffu, s1, 1);
        s1 += __shfl_xor_sync(0xffffffffu, s1, 2);
        if ((lane & 3) == 0) {
            atomicAdd(&ss[r0], s0);
            atomicAdd(&ss[r0 + 8], s1);
        }
    }
    __syncthreads();

#pragma unroll
    for (int mi = 0; mi < 2; ++mi) {
        const int r0 = wm * 32 + mi * 16 + lr;
        const float sc0 = 1.0f / fmaxf(sqrtf(ss[r0]), 1e-12f);
        const float sc1 = 1.0f / fmaxf(sqrtf(ss[r0 + 8]), 1e-12f);
#pragma unroll
        for (int ni = 0; ni < 8; ++ni) {
            const int col = wn * 64 + ni * 8 + lc;
            uint32_t h, l;
            split2(d[mi][ni][0] * sc0, d[mi][ni][1] * sc0, h, l);
            *(uint32_t*)(smem + C_HH + (size_t)(r0 * RSH + col) * 2) = h;
            *(uint32_t*)(smem + C_HL + (size_t)(r0 * RSH + col) * 2) = l;
            split2(d[mi][ni][2] * sc1, d[mi][ni][3] * sc1, h, l);
            *(uint32_t*)(smem + C_HH + (size_t)((r0 + 8) * RSH + col) * 2) = h;
            *(uint32_t*)(smem + C_HL + (size_t)((r0 + 8) * RSH + col) * 2) = l;
        }
    }
    CP_WAIT0();
    __syncthreads();

    float e[2][4][4];
#pragma unroll
    for (int i = 0; i < 2; ++i)
#pragma unroll
        for (int j = 0; j < 4; ++j)
#pragma unroll
            for (int k = 0; k < 4; ++k) e[i][j][k] = 0.f;

#pragma unroll
    for (int ch = 0; ch < 4; ++ch) {
        const int kb = ch * 64;
        const uint32_t fH = sb + C_FC, fL = fH + 18432;
#pragma unroll
        for (int ks = 0; ks < 4; ++ks) {
            uint32_t ah[2][4], al[2][4];
#pragma unroll
            for (int mi = 0; mi < 2; ++mi) {
                uint32_t ad = (uint32_t)((wm * 32 + mi * 16 + aro) * RSH
                                         + kb + ks * 16 + aco) * 2;
                ldmx4(ah[mi], sb + C_HH + ad);
                ldmx4(al[mi], sb + C_HL + ad);
            }
#pragma unroll
            for (int nip = 0; nip < 2; ++nip) {
                uint32_t bd = (uint32_t)((wn * 32 + nip * 16 + bro) * RSA
                                         + ks * 16 + bco) * 2;
                uint32_t th[4], tl[4];
                ldmx4(th, fH + bd);
                ldmx4(tl, fL + bd);
#pragma unroll
                for (int sub = 0; sub < 2; ++sub) {
                    const int ni = 2 * nip + sub;
#pragma unroll
                    for (int mi = 0; mi < 2; ++mi) {
                        mma16816(e[mi][ni], ah[mi], th[2 * sub], th[2 * sub + 1]);
                        mma16816(e[mi][ni], ah[mi], tl[2 * sub], tl[2 * sub + 1]);
                        mma16816(e[mi][ni], al[mi], th[2 * sub], th[2 * sub + 1]);
                    }
                }
            }
        }
        if (ch < 3) {
            __syncthreads();
            ISSUE_FC(ch + 1);
            CP_COMMIT();
            CP_WAIT0();
            __syncthreads();
        }
    }

#pragma unroll
    for (int mi = 0; mi < 2; ++mi) {
        const int row = m0 + wm * 32 + mi * 16 + lr;
#pragma unroll
        for (int ni = 0; ni < 4; ++ni) {
            const int col = wn * 32 + ni * 8 + lc;
            const float b0 = __ldg(&fcb[col]), b1 = __ldg(&fcb[col + 1]);
            *(float2*)(out + (size_t)row * 128 + col) =
                make_float2(e[mi][ni][0] + b0, e[mi][ni][1] + b1);
            *(float2*)(out + (size_t)(row + 8) * 128 + col) =
                make_float2(e[mi][ni][2] + b0, e[mi][ni][3] + b1);
        }
    }
}

// ---------------------------------------------------------------------------
extern "C" void kernel_launch(void* const* d_in, const int* in_sizes, int n_in,
                              void* d_out, int out_size)
{
    const float* emb      = (const float*)d_in[0];
    const float* w_self0  = (const float*)d_in[1];
    const float* b_self0  = (const float*)d_in[2];
    const float* w_neigh0 = (const float*)d_in[3];
    const float* b_neigh0 = (const float*)d_in[4];
    const float* w_self1  = (const float*)d_in[5];
    const float* b_self1  = (const float*)d_in[6];
    const float* w_neigh1 = (const float*)d_in[7];
    const float* b_neigh1 = (const float*)d_in[8];
    const float* fc_w     = (const float*)d_in[9];
    const float* fc_b     = (const float*)d_in[10];
    const int*   nodeids  = (const int*)d_in[11];
    const int*   neigh1   = (const int*)d_in[12];
    const int*   neigh2   = (const int*)d_in[13];
    float*       out      = (float*)d_out;

    __nv_bfloat16 *WHI, *WLO;
    float *F0, *F1;
    cudaGetSymbolAddress((void**)&WHI, g_whi);
    cudaGetSymbolAddress((void**)&WLO, g_wlo);
    cudaGetSymbolAddress((void**)&F0, g_F0);
    cudaGetSymbolAddress((void**)&F1, g_F1);

    cudaFuncSetAttribute(layer0_k, cudaFuncAttributeMaxDynamicSharedMemorySize, G_SMEM);
    cudaFuncSetAttribute(l1fc_k,   cudaFuncAttributeMaxDynamicSharedMemorySize, L_SMEM);

    layer0_k<<<2048, 256, G_SMEM>>>(emb, nodeids, neigh1, neigh2,
                                    w_self0, w_neigh0, w_self1, w_neigh1, fc_w,
                                    WHI, WLO, WHI, WLO,
                                    b_self0, b_neigh0, F0, F1);

    l1fc_k<<<B_ROOT / 64, 256, L_SMEM>>>(F0, F1,
                                         WHI + 65536, WLO + 65536,
                                         b_self1, b_neigh1,
                                         WHI + 131072, WLO + 131072,
                                         fc_b, out);
}

// round 14
// speedup vs baseline: 1.0476x; 1.0476x over previous
#include <cuda_runtime.h>
#include <cuda_bf16.h>
#include <cstdint>

// ---------------------------------------------------------------------------
// GraphSAGE, mma.sync bf16 hi/lo (3-product fp32-accurate). SINGLE LAUNCH:
//   bids 0..2047  : layer0 (weight pre-split by first 8 CTAs + flag), 4 GEMM
//                   segments CONTIGUOUS (R12 order), release done-counter.
//   bids 2048..2303: fused layer1 + L2-norm + FC; poll done==2048 (acquire),
//                   W1 chunk-0 prefetched during the drain. Last one resets
//                   all flags for the next graph replay.
// ---------------------------------------------------------------------------

#define B_ROOT 16384
#define R1     49152
#define RSA    72            // k64 tile row stride (bf16 elems)
#define RSC    40            // k32 tile row stride (bf16 elems)
#define RSH    264           // h row stride

// layer0 smem (bytes)
#define GA(b)  ((b) * 18432)                 // A: hi +0, lo +9216
#define GW(b)  (36864 + (b) * 36864)         // W: hi +0, lo +18432
#define G_SMEM 110592
// l1fc smem (bytes) — fits inside G_SMEM
#define C_ASH  0
#define C_ASL  5120
#define C_ANH  10240
#define C_ANL  15360
#define C_W(b) (20480 + (b) * 40960)
#define C_HH   0
#define C_HL   33792
#define C_FC   67584
#define C_SS   104448

// ---------------- scratch ----------------------------------------------------
__device__ float g_F0[B_ROOT * 256];
__device__ float g_F1[R1 * 256];
__device__ __nv_bfloat16 g_whi[5 * 32768];
__device__ __nv_bfloat16 g_wlo[5 * 32768];
__device__ unsigned g_wflag;   // converter completions (8)
__device__ unsigned g_done;    // layer0 CTA completions (2048)
__device__ unsigned g_fin;     // l1fc CTA completions (256)

// ---------------- helpers ----------------------------------------------------
__device__ __forceinline__ uint32_t smem_u32(const void* p) {
    uint32_t a;
    asm("{ .reg .u64 t; cvta.to.shared.u64 t, %1; cvt.u32.u64 %0, t; }"
        : "=r"(a) : "l"(p));
    return a;
}
__device__ __forceinline__ void split2(float a, float b, uint32_t& h, uint32_t& l) {
    __nv_bfloat16 ah = __float2bfloat16_rn(a), bh = __float2bfloat16_rn(b);
    __nv_bfloat16 al = __float2bfloat16_rn(a - __bfloat162float(ah));
    __nv_bfloat16 bl = __float2bfloat16_rn(b - __bfloat162float(bh));
    __nv_bfloat162 ph = __halves2bfloat162(ah, bh);
    __nv_bfloat162 pl = __halves2bfloat162(al, bl);
    h = *reinterpret_cast<uint32_t*>(&ph);
    l = *reinterpret_cast<uint32_t*>(&pl);
}
__device__ __forceinline__ void split8(const float* v, uint4& h4, uint4& l4) {
    uint32_t h[4], l[4];
#pragma unroll
    for (int i = 0; i < 4; ++i) split2(v[2 * i], v[2 * i + 1], h[i], l[i]);
    h4 = make_uint4(h[0], h[1], h[2], h[3]);
    l4 = make_uint4(l[0], l[1], l[2], l[3]);
}
__device__ __forceinline__ void mma16816(float* d, const uint32_t* a,
                                         uint32_t b0, uint32_t b1) {
    asm volatile(
        "mma.sync.aligned.m16n8k16.row.col.f32.bf16.bf16.f32 "
        "{%0,%1,%2,%3}, {%4,%5,%6,%7}, {%8,%9}, {%0,%1,%2,%3};"
        : "+f"(d[0]), "+f"(d[1]), "+f"(d[2]), "+f"(d[3])
        : "r"(a[0]), "r"(a[1]), "r"(a[2]), "r"(a[3]), "r"(b0), "r"(b1));
}
__device__ __forceinline__ void ldmx4(uint32_t* r, uint32_t a) {
    asm volatile("ldmatrix.sync.aligned.m8n8.x4.shared.b16 {%0,%1,%2,%3}, [%4];"
                 : "=r"(r[0]), "=r"(r[1]), "=r"(r[2]), "=r"(r[3]) : "r"(a));
}
__device__ __forceinline__ void cp16(uint32_t dst, const void* src) {
    asm volatile("cp.async.cg.shared.global [%0], [%1], 16;" :: "r"(dst), "l"(src));
}
#define CP_COMMIT() asm volatile("cp.async.commit_group;" ::: "memory")
#define CP_WAIT0()  asm volatile("cp.async.wait_group 0;"  ::: "memory")

// ---------------- layer-0 GEMM body (R12, proven) ------------------------------
template <int GATHER, int KF>
__device__ __forceinline__ void
gemm_body(char* smem, const float* __restrict__ A, const int* __restrict__ idx,
          const __nv_bfloat16* __restrict__ w_hi, const __nv_bfloat16* __restrict__ w_lo,
          const float* __restrict__ bias,
          float* __restrict__ C, int ldc, int col_off, int m0)
{
    const uint32_t sb = smem_u32(smem);
    const int tid = threadIdx.x, lane = tid & 31, wid = tid >> 5;
    const int wm = wid >> 2, wn = wid & 3;
    const int lr = lane >> 2, lc = (lane & 3) * 2;
    const int g  = lane >> 3, lm = lane & 7;
    const int aro = ((g & 1) << 3) + lm, aco = (g >> 1) << 3;
    const int bro = ((g >> 1) << 3) + lm, bco = (g & 1) << 3;
    const int r  = tid >> 2, cq = (tid & 3) * 16;

    auto ISSUE_W = [&](int ch, int buf) {
        const int kb = ch * 64;
#pragma unroll
        for (int i = 0; i < 8; ++i) {
            int o = tid + i * 256;
            int plane = o >> 10, ix = o & 1023;
            int row = ix >> 3, c8 = (ix & 7) * 8;
            const __nv_bfloat16* src =
                (plane ? w_lo : w_hi) + (size_t)row * 256 + kb + c8;
            cp16(sb + GW(buf) + (plane ? 18432 : 0)
                 + (uint32_t)(row * RSA + c8) * 2, src);
        }
    };

    int rows[KF];
    if (GATHER == 0)      rows[0] = idx[m0 + r];
    else {
#pragma unroll
        for (int j = 0; j < KF; ++j) rows[j] = idx[(size_t)(m0 + r) * KF + j];
    }

    float v[16];
    auto PREF = [&](int ch) {
        const int kb = ch * 64;
        if (GATHER == 0) {
            const float4* p = (const float4*)(A + (size_t)rows[0] * 256 + kb + cq);
            float4 t0 = __ldg(p), t1 = __ldg(p + 1), t2 = __ldg(p + 2), t3 = __ldg(p + 3);
            v[0]  = t0.x; v[1]  = t0.y; v[2]  = t0.z; v[3]  = t0.w;
            v[4]  = t1.x; v[5]  = t1.y; v[6]  = t1.z; v[7]  = t1.w;
            v[8]  = t2.x; v[9]  = t2.y; v[10] = t2.z; v[11] = t2.w;
            v[12] = t3.x; v[13] = t3.y; v[14] = t3.z; v[15] = t3.w;
        } else {
#pragma unroll
            for (int i = 0; i < 16; ++i) v[i] = 0.f;
#pragma unroll
            for (int h = 0; h < 2; ++h) {
                float4 t[2 * KF];
#pragma unroll
                for (int j = 0; j < KF; ++j) {
                    const float4* p = (const float4*)(A + (size_t)rows[j] * 256
                                                      + kb + cq + h * 8);
                    t[j * 2]     = __ldg(p);
                    t[j * 2 + 1] = __ldg(p + 1);
                }
#pragma unroll
                for (int j = 0; j < KF; ++j)
#pragma unroll
                    for (int q = 0; q < 2; ++q) {
                        const float4 f = t[j * 2 + q];
                        const int o = h * 8 + q * 4;
                        v[o + 0] += f.x; v[o + 1] += f.y;
                        v[o + 2] += f.z; v[o + 3] += f.w;
                    }
            }
        }
    };
    auto STORE = [&](int buf) {
        const float s = 1.0f / (float)KF;
        float w[16];
#pragma unroll
        for (int i = 0; i < 16; ++i) w[i] = v[i] * s;
        uint4 h0, l0, h1, l1;
        split8(w, h0, l0);
        split8(w + 8, h1, l1);
        char* base = smem + GA(buf) + (size_t)(r * RSA + cq) * 2;
        *(uint4*)(base)              = h0;
        *(uint4*)(base + 16)         = h1;
        *(uint4*)(base + 9216)       = l0;
        *(uint4*)(base + 9216 + 16)  = l1;
    };

    float d[2][4][4];
#pragma unroll
    for (int i = 0; i < 2; ++i)
#pragma unroll
        for (int j = 0; j < 4; ++j)
#pragma unroll
            for (int k = 0; k < 4; ++k) d[i][j][k] = 0.f;

    ISSUE_W(0, 0);
    CP_COMMIT();
    PREF(0);
    STORE(0);
    CP_WAIT0();
    __syncthreads();

#pragma unroll
    for (int ch = 0; ch < 4; ++ch) {
        const int cb = ch & 1, nb = cb ^ 1;
        if (ch < 3) {
            ISSUE_W(ch + 1, nb);
            CP_COMMIT();
            PREF(ch + 1);
        }
        const uint32_t aH = sb + GA(cb), aL = aH + 9216;
        const uint32_t wH = sb + GW(cb), wL = wH + 18432;
#pragma unroll
        for (int ks = 0; ks < 4; ++ks) {
            uint32_t ah[2][4], al[2][4];
#pragma unroll
            for (int mi = 0; mi < 2; ++mi) {
                uint32_t ad = (uint32_t)((wm * 32 + mi * 16 + aro) * RSA
                                         + ks * 16 + aco) * 2;
                ldmx4(ah[mi], aH + ad);
                ldmx4(al[mi], aL + ad);
            }
            uint32_t bh[4][2], bl[4][2];
#pragma unroll
            for (int nip = 0; nip < 2; ++nip) {
                uint32_t bd = (uint32_t)((wn * 32 + nip * 16 + bro) * RSA
                                         + ks * 16 + bco) * 2;
                uint32_t t4[4];
                ldmx4(t4, wH + bd);
                bh[2 * nip][0] = t4[0]; bh[2 * nip][1] = t4[1];
                bh[2 * nip + 1][0] = t4[2]; bh[2 * nip + 1][1] = t4[3];
                ldmx4(t4, wL + bd);
                bl[2 * nip][0] = t4[0]; bl[2 * nip][1] = t4[1];
                bl[2 * nip + 1][0] = t4[2]; bl[2 * nip + 1][1] = t4[3];
            }
#pragma unroll
            for (int ni = 0; ni < 4; ++ni)
#pragma unroll
                for (int mi = 0; mi < 2; ++mi) {
                    mma16816(d[mi][ni], ah[mi], bh[ni][0], bh[ni][1]);
                    mma16816(d[mi][ni], ah[mi], bl[ni][0], bl[ni][1]);
                    mma16816(d[mi][ni], al[mi], bh[ni][0], bh[ni][1]);
                }
        }
        if (ch < 3) {
            STORE(nb);
            CP_WAIT0();
        }
        __syncthreads();
    }

#pragma unroll
    for (int mi = 0; mi < 2; ++mi) {
        const int row = m0 + wm * 32 + mi * 16 + lr;
#pragma unroll
        for (int ni = 0; ni < 4; ++ni) {
            const int col = wn * 32 + ni * 8 + lc;
            const float b0 = __ldg(&bias[col]), b1 = __ldg(&bias[col + 1]);
            *(float2*)(C + (size_t)row * ldc + col_off + col) =
                make_float2(fmaxf(d[mi][ni][0] + b0, 0.f),
                            fmaxf(d[mi][ni][1] + b1, 0.f));
            *(float2*)(C + (size_t)(row + 8) * ldc + col_off + col) =
                make_float2(fmaxf(d[mi][ni][2] + b0, 0.f),
                            fmaxf(d[mi][ni][3] + b1, 0.f));
        }
    }
}

// ---------------- l1fc body (R12, proven) ---------------------------------------
__device__ __forceinline__ void
l1fc_body(char* smem, int m0,
          const float* __restrict__ F0, const float* __restrict__ F1,
          const __nv_bfloat16* __restrict__ w1_hi, const __nv_bfloat16* __restrict__ w1_lo,
          const float* __restrict__ bS, const float* __restrict__ bN,
          const __nv_bfloat16* __restrict__ fc_hi, const __nv_bfloat16* __restrict__ fc_lo,
          const float* __restrict__ fcb, float* __restrict__ out)
{
    const uint32_t sb = smem_u32(smem);
    const int tid = threadIdx.x, lane = tid & 31, wid = tid >> 5;
    const int wm = wid >> 2, wn = wid & 3;
    const int lr = lane >> 2, lc = (lane & 3) * 2;
    const int g  = lane >> 3, lm = lane & 7;
    const int aro = ((g & 1) << 3) + lm, aco = (g >> 1) << 3;
    const int bro = ((g >> 1) << 3) + lm, bco = (g & 1) << 3;

    const bool isSelf = tid < 128;
    const int lt = tid & 127;
    const int r = lt >> 1, cq = (lt & 1) * 16;

    auto ISSUE_W = [&](int ch, int buf) {
        const int kb = ch * 32;
#pragma unroll
        for (int i = 0; i < 8; ++i) {
            int o = tid + i * 256;
            int plane = o >> 10, ix = o & 1023;
            int row = ix >> 2, c8 = (ix & 3) * 8;
            const __nv_bfloat16* src =
                (plane ? w1_lo : w1_hi) + (size_t)row * 256 + kb + c8;
            cp16(sb + C_W(buf) + (plane ? 20480 : 0)
                 + (uint32_t)(row * RSC + c8) * 2, src);
        }
    };

    float v[16];
    auto PREF = [&](int ch) {
        const int kb = ch * 32;
        if (isSelf) {
            const float4* p = (const float4*)(F0 + (size_t)(m0 + r) * 256 + kb + cq);
            float4 t0 = __ldg(p), t1 = __ldg(p + 1), t2 = __ldg(p + 2), t3 = __ldg(p + 3);
            v[0]  = t0.x; v[1]  = t0.y; v[2]  = t0.z; v[3]  = t0.w;
            v[4]  = t1.x; v[5]  = t1.y; v[6]  = t1.z; v[7]  = t1.w;
            v[8]  = t2.x; v[9]  = t2.y; v[10] = t2.z; v[11] = t2.w;
            v[12] = t3.x; v[13] = t3.y; v[14] = t3.z; v[15] = t3.w;
        } else {
            float4 t[12];
#pragma unroll
            for (int j = 0; j < 3; ++j) {
                const float4* p = (const float4*)(F1
                    + (size_t)((m0 + r) * 3 + j) * 256 + kb + cq);
#pragma unroll
                for (int q = 0; q < 4; ++q) t[j * 4 + q] = __ldg(p + q);
            }
#pragma unroll
            for (int i = 0; i < 16; ++i) v[i] = 0.f;
#pragma unroll
            for (int j = 0; j < 3; ++j)
#pragma unroll
                for (int q = 0; q < 4; ++q) {
                    const float4 f = t[j * 4 + q];
                    v[q * 4 + 0] += f.x; v[q * 4 + 1] += f.y;
                    v[q * 4 + 2] += f.z; v[q * 4 + 3] += f.w;
                }
#pragma unroll
            for (int i = 0; i < 16; ++i) v[i] *= (1.0f / 3.0f);
        }
    };
    auto STORE = [&]() {
        uint4 h0, l0, h1, l1;
        split8(v, h0, l0);
        split8(v + 8, h1, l1);
        char* base = smem + (isSelf ? C_ASH : C_ANH) + (size_t)(r * RSC + cq) * 2;
        *(uint4*)(base)             = h0;
        *(uint4*)(base + 16)        = h1;
        *(uint4*)(base + 5120)      = l0;
        *(uint4*)(base + 5120 + 16) = l1;
    };

    float d[2][8][4];
#pragma unroll
    for (int i = 0; i < 2; ++i)
#pragma unroll
        for (int j = 0; j < 8; ++j)
#pragma unroll
            for (int k = 0; k < 4; ++k) d[i][j][k] = 0.f;

    // W chunk 0 was prefetched by caller (pre-poll). Finish A staging.
    PREF(0);
    STORE();
    CP_WAIT0();
    __syncthreads();

#pragma unroll
    for (int ch = 0; ch < 8; ++ch) {
        const int cb = ch & 1, nb = cb ^ 1;
        if (ch < 7) {
            ISSUE_W(ch + 1, nb);
            CP_COMMIT();
            PREF(ch + 1);
        }
        const uint32_t aH = sb + (wn < 2 ? C_ASH : C_ANH);
        const uint32_t aL = aH + 5120;
        const uint32_t wH = sb + C_W(cb), wL = wH + 20480;
#pragma unroll
        for (int ks = 0; ks < 2; ++ks) {
            uint32_t ah[2][4], al[2][4];
#pragma unroll
            for (int mi = 0; mi < 2; ++mi) {
                uint32_t ad = (uint32_t)((wm * 32 + mi * 16 + aro) * RSC
                                         + ks * 16 + aco) * 2;
                ldmx4(ah[mi], aH + ad);
                ldmx4(al[mi], aL + ad);
            }
#pragma unroll
            for (int nip = 0; nip < 4; ++nip) {
                uint32_t bd = (uint32_t)((wn * 64 + nip * 16 + bro) * RSC
                                         + ks * 16 + bco) * 2;
                uint32_t th[4], tl[4];
                ldmx4(th, wH + bd);
                ldmx4(tl, wL + bd);
#pragma unroll
                for (int sub = 0; sub < 2; ++sub) {
                    const int ni = 2 * nip + sub;
#pragma unroll
                    for (int mi = 0; mi < 2; ++mi) {
                        mma16816(d[mi][ni], ah[mi], th[2 * sub], th[2 * sub + 1]);
                        mma16816(d[mi][ni], ah[mi], tl[2 * sub], tl[2 * sub + 1]);
                        mma16816(d[mi][ni], al[mi], th[2 * sub], th[2 * sub + 1]);
                    }
                }
            }
        }
        __syncthreads();
        if (ch < 7) {
            STORE();
            CP_WAIT0();
            __syncthreads();
        }
    }

    auto ISSUE_FC = [&](int ch) {
        const int kb = ch * 64;
#pragma unroll
        for (int i = 0; i < 8; ++i) {
            int o = tid + i * 256;
            int plane = o >> 10, ix = o & 1023;
            int row = ix >> 3, c8 = (ix & 7) * 8;
            const __nv_bfloat16* src = (plane ? fc_lo : fc_hi)
                                     + (size_t)row * 256 + kb + c8;
            cp16(sb + C_FC + (plane ? 18432 : 0)
                 + (uint32_t)(row * RSA + c8) * 2, src);
        }
    };
    ISSUE_FC(0);
    CP_COMMIT();

    float* ss = (float*)(smem + C_SS);
    if (tid < 64) ss[tid] = 0.f;
    __syncthreads();

#pragma unroll
    for (int mi = 0; mi < 2; ++mi) {
        const int r0 = wm * 32 + mi * 16 + lr;
        float s0 = 0.f, s1 = 0.f;
#pragma unroll
        for (int ni = 0; ni < 8; ++ni) {
            const int col = wn * 64 + ni * 8 + lc;
            const float b0 = (col < 128) ? bS[col] : bN[col - 128];
            const float b1 = (col + 1 < 128) ? bS[col + 1] : bN[col - 127];
            d[mi][ni][0] = fmaxf(d[mi][ni][0] + b0, 0.f);
            d[mi][ni][1] = fmaxf(d[mi][ni][1] + b1, 0.f);
            d[mi][ni][2] = fmaxf(d[mi][ni][2] + b0, 0.f);
            d[mi][ni][3] = fmaxf(d[mi][ni][3] + b1, 0.f);
            s0 += d[mi][ni][0] * d[mi][ni][0] + d[mi][ni][1] * d[mi][ni][1];
            s1 += d[mi][ni][2] * d[mi][ni][2] + d[mi][ni][3] * d[mi][ni][3];
        }
        s0 += __shfl_xor_sync(0xffffffffu, s0, 1);
        s0 += __shfl_xor_sync(0xffffffffu, s0, 2);
        s1 += __shfl_xor_sync(0xffffffffu, s1, 1);
        s1 += __shfl_xor_sync(0xffffffffu, s1, 2);
        if ((lane & 3) == 0) {
            atomicAdd(&ss[r0], s0);
            atomicAdd(&ss[r0 + 8], s1);
        }
    }
    __syncthreads();

#pragma unroll
    for (int mi = 0; mi < 2; ++mi) {
        const int r0 = wm * 32 + mi * 16 + lr;
        const float sc0 = 1.0f / fmaxf(sqrtf(ss[r0]), 1e-12f);
        const float sc1 = 1.0f / fmaxf(sqrtf(ss[r0 + 8]), 1e-12f);
#pragma unroll
        for (int ni = 0; ni < 8; ++ni) {
            const int col = wn * 64 + ni * 8 + lc;
            uint32_t h, l;
            split2(d[mi][ni][0] * sc0, d[mi][ni][1] * sc0, h, l);
            *(uint32_t*)(smem + C_HH + (size_t)(r0 * RSH + col) * 2) = h;
            *(uint32_t*)(smem + C_HL + (size_t)(r0 * RSH + col) * 2) = l;
            split2(d[mi][ni][2] * sc1, d[mi][ni][3] * sc1, h, l);
            *(uint32_t*)(smem + C_HH + (size_t)((r0 + 8) * RSH + col) * 2) = h;
            *(uint32_t*)(smem + C_HL + (size_t)((r0 + 8) * RSH + col) * 2) = l;
        }
    }
    CP_WAIT0();
    __syncthreads();

    float e[2][4][4];
#pragma unroll
    for (int i = 0; i < 2; ++i)
#pragma unroll
        for (int j = 0; j < 4; ++j)
#pragma unroll
            for (int k = 0; k < 4; ++k) e[i][j][k] = 0.f;

#pragma unroll
    for (int ch = 0; ch < 4; ++ch) {
        const int kb = ch * 64;
        const uint32_t fH = sb + C_FC, fL = fH + 18432;
#pragma unroll
        for (int ks = 0; ks < 4; ++ks) {
            uint32_t ah[2][4], al[2][4];
#pragma unroll
            for (int mi = 0; mi < 2; ++mi) {
                uint32_t ad = (uint32_t)((wm * 32 + mi * 16 + aro) * RSH
                                         + kb + ks * 16 + aco) * 2;
                ldmx4(ah[mi], sb + C_HH + ad);
                ldmx4(al[mi], sb + C_HL + ad);
            }
#pragma unroll
            for (int nip = 0; nip < 2; ++nip) {
                uint32_t bd = (uint32_t)((wn * 32 + nip * 16 + bro) * RSA
                                         + ks * 16 + bco) * 2;
                uint32_t th[4], tl[4];
                ldmx4(th, fH + bd);
                ldmx4(tl, fL + bd);
#pragma unroll
                for (int sub = 0; sub < 2; ++sub) {
                    const int ni = 2 * nip + sub;
#pragma unroll
                    for (int mi = 0; mi < 2; ++mi) {
                        mma16816(e[mi][ni], ah[mi], th[2 * sub], th[2 * sub + 1]);
                        mma16816(e[mi][ni], ah[mi], tl[2 * sub], tl[2 * sub + 1]);
                        mma16816(e[mi][ni], al[mi], th[2 * sub], th[2 * sub + 1]);
                    }
                }
            }
        }
        if (ch < 3) {
            __syncthreads();
            ISSUE_FC(ch + 1);
            CP_COMMIT();
            CP_WAIT0();
            __syncthreads();
        }
    }

#pragma unroll
    for (int mi = 0; mi < 2; ++mi) {
        const int row = m0 + wm * 32 + mi * 16 + lr;
#pragma unroll
        for (int ni = 0; ni < 4; ++ni) {
            const int col = wn * 32 + ni * 8 + lc;
            const float b0 = __ldg(&fcb[col]), b1 = __ldg(&fcb[col + 1]);
            *(float2*)(out + (size_t)row * 128 + col) =
                make_float2(e[mi][ni][0] + b0, e[mi][ni][1] + b1);
            *(float2*)(out + (size_t)(row + 8) * 128 + col) =
                make_float2(e[mi][ni][2] + b0, e[mi][ni][3] + b1);
        }
    }
}

// ---------------- single fused kernel --------------------------------------------
__global__ void __launch_bounds__(256, 2)
fused_k(const float* __restrict__ emb,
        const int* __restrict__ nodeids, const int* __restrict__ neigh1,
        const int* __restrict__ neigh2,
        const float* __restrict__ ws0, const float* __restrict__ wn0,
        const float* __restrict__ ws1f, const float* __restrict__ wn1f,
        const float* __restrict__ fcwf,
        __nv_bfloat16* __restrict__ whi, __nv_bfloat16* __restrict__ wlo,
        const float* __restrict__ bs0, const float* __restrict__ bn0,
        const float* __restrict__ bs1, const float* __restrict__ bn1,
        const float* __restrict__ fcb,
        float* __restrict__ F0, float* __restrict__ F1, float* __restrict__ out)
{
    extern __shared__ char smem[];
    const int bid = blockIdx.x;
    const int tid = threadIdx.x;

    if (bid < 2048) {
        // ---- converter segment ----------------------------------------------
        if (bid < 8) {
            const float* src[5] = {ws0, wn0, ws1f, wn1f, fcwf};
#pragma unroll
            for (int i = 0; i < 20; ++i) {
                int idx4 = bid * 5120 + i * 256 + tid;
                int base = idx4 * 4;
                float4 f = __ldg((const float4*)(src[base >> 15] + (base & 32767)));
                uint32_t h0, l0, h1, l1;
                split2(f.x, f.y, h0, l0);
                split2(f.z, f.w, h1, l1);
                *(uint2*)(whi + base) = make_uint2(h0, h1);
                *(uint2*)(wlo + base) = make_uint2(l0, l1);
            }
            __syncthreads();
            if (tid == 0) {
                unsigned old;
                asm volatile("atom.add.release.gpu.u32 %0, [%1], 1;"
                             : "=r"(old) : "l"(&g_wflag) : "memory");
            }
        }
        if (tid == 0) {
            unsigned val;
            do {
                asm volatile("ld.acquire.gpu.u32 %0, [%1];"
                             : "=r"(val) : "l"(&g_wflag) : "memory");
                if (val >= 8u) break;
                __nanosleep(64);
            } while (true);
        }
        __syncthreads();

        // ---- layer0 GEMM segments (R12 contiguous order) ----------------------
        if (bid < 768) {
            gemm_body<1, 5>(smem, emb, neigh2, whi + 32768, wlo + 32768, bn0,
                            F1, 256, 128, bid * 64);
        } else if (bid < 1536) {
            gemm_body<0, 1>(smem, emb, neigh1, whi, wlo, bs0,
                            F1, 256, 0, (bid - 768) * 64);
        } else if (bid < 1792) {
            gemm_body<1, 3>(smem, emb, neigh1, whi + 32768, wlo + 32768, bn0,
                            F0, 256, 128, (bid - 1536) * 64);
        } else {
            gemm_body<0, 1>(smem, emb, nodeids, whi, wlo, bs0,
                            F0, 256, 0, (bid - 1792) * 64);
        }

        __syncthreads();
        if (tid == 0) {
            unsigned old;
            asm volatile("atom.add.release.gpu.u32 %0, [%1], 1;"
                         : "=r"(old) : "l"(&g_done) : "memory");
        }
        return;
    }

    // ======== l1fc part (bids 2048..2303) ======================================
    const int m0 = (bid - 2048) * 64;
    const __nv_bfloat16* w1_hi = whi + 65536;
    const __nv_bfloat16* w1_lo = wlo + 65536;
    const __nv_bfloat16* fc_hi = whi + 131072;
    const __nv_bfloat16* fc_lo = wlo + 131072;

    // wait for weights, then prefetch W1 chunk 0 while layer0 drains
    if (tid == 0) {
        unsigned val;
        do {
            asm volatile("ld.acquire.gpu.u32 %0, [%1];"
                         : "=r"(val) : "l"(&g_wflag) : "memory");
            if (val >= 8u) break;
            __nanosleep(64);
        } while (true);
    }
    __syncthreads();
    {
        const uint32_t sb = smem_u32(smem);
#pragma unroll
        for (int i = 0; i < 8; ++i) {
            int o = tid + i * 256;
            int plane = o >> 10, ix = o & 1023;
            int row = ix >> 2, c8 = (ix & 3) * 8;
            const __nv_bfloat16* src =
                (plane ? w1_lo : w1_hi) + (size_t)row * 256 + c8;
            cp16(sb + C_W(0) + (plane ? 20480 : 0)
                 + (uint32_t)(row * RSC + c8) * 2, src);
        }
        CP_COMMIT();
    }
    // wait for all 2048 layer0 CTAs
    if (tid == 0) {
        unsigned val;
        do {
            asm volatile("ld.acquire.gpu.u32 %0, [%1];"
                         : "=r"(val) : "l"(&g_done) : "memory");
            if (val >= 2048u) break;
            __nanosleep(128);
        } while (true);
    }
    __syncthreads();

    l1fc_body(smem, m0, F0, F1, w1_hi, w1_lo, bs1, bn1, fc_hi, fc_lo, fcb, out);

    // last finisher resets flags for the next graph replay
    __syncthreads();
    if (tid == 0) {
        unsigned old;
        asm volatile("atom.add.release.gpu.u32 %0, [%1], 1;"
                     : "=r"(old) : "l"(&g_fin) : "memory");
        if (old == 255u) {
            asm volatile("st.relaxed.gpu.u32 [%0], 0;" :: "l"(&g_wflag) : "memory");
            asm volatile("st.relaxed.gpu.u32 [%0], 0;" :: "l"(&g_done) : "memory");
            asm volatile("st.relaxed.gpu.u32 [%0], 0;" :: "l"(&g_fin) : "memory");
        }
    }
}

// ---------------------------------------------------------------------------
extern "C" void kernel_launch(void* const* d_in, const int* in_sizes, int n_in,
                              void* d_out, int out_size)
{
    const float* emb      = (const float*)d_in[0];
    const float* w_self0  = (const float*)d_in[1];
    const float* b_self0  = (const float*)d_in[2];
    const float* w_neigh0 = (const float*)d_in[3];
    const float* b_neigh0 = (const float*)d_in[4];
    const float* w_self1  = (const float*)d_in[5];
    const float* b_self1  = (const float*)d_in[6];
    const float* w_neigh1 = (const float*)d_in[7];
    const float* b_neigh1 = (const float*)d_in[8];
    const float* fc_w     = (const float*)d_in[9];
    const float* fc_b     = (const float*)d_in[10];
    const int*   nodeids  = (const int*)d_in[11];
    const int*   neigh1   = (const int*)d_in[12];
    const int*   neigh2   = (const int*)d_in[13];
    float*       out      = (float*)d_out;

    __nv_bfloat16 *WHI, *WLO;
    float *F0, *F1;
    cudaGetSymbolAddress((void**)&WHI, g_whi);
    cudaGetSymbolAddress((void**)&WLO, g_wlo);
    cudaGetSymbolAddress((void**)&F0, g_F0);
    cudaGetSymbolAddress((void**)&F1, g_F1);

    cudaFuncSetAttribute(fused_k, cudaFuncAttributeMaxDynamicSharedMemorySize, G_SMEM);

    fused_k<<<2304, 256, G_SMEM>>>(emb, nodeids, neigh1, neigh2,
                                   w_self0, w_neigh0, w_self1, w_neigh1, fc_w,
                                   WHI, WLO,
                                   b_self0, b_neigh0, b_self1, b_neigh1, fc_b,
                                   F0, F1, out);
}

// round 15
// speedup vs baseline: 1.1601x; 1.1074x over previous
#include <cuda_runtime.h>
#include <cuda_bf16.h>
#include <cstdint>

// ---------------------------------------------------------------------------
// GraphSAGE, mma.sync bf16 hi/lo (3-product fp32-accurate). Two launches (R12):
// layer0_k: weight pre-split fused (8 converter CTAs + acquire flag); 4 GEMM
//   segments CONTIGUOUS; gemm_body = 256 thr, M64 x N128, K=256 in 4 chunks,
//   2 CTAs/SM. NEW: gather lanes read interleaved float4s (coalesced 64B per
//   quad per instr -> half the L1tex wavefronts on the 360MB gather stream).
// l1fc_k: 256 thr, 2 CTAs/SM; stage1 M64 x N256 layer-1 (k32 chunks), row
//   L2-norm, stage2 FC — all fused.
// ---------------------------------------------------------------------------

#define B_ROOT 16384
#define R1     49152
#define RSA    72            // k64 tile row stride (bf16 elems)
#define RSC    40            // k32 tile row stride (bf16 elems)
#define RSH    264           // h row stride

// layer0 smem (bytes)
#define GA(b)  ((b) * 18432)                 // A: hi +0, lo +9216
#define GW(b)  (36864 + (b) * 36864)         // W: hi +0, lo +18432
#define G_SMEM 110592
// l1fc smem (bytes)
#define C_ASH  0
#define C_ASL  5120
#define C_ANH  10240
#define C_ANL  15360
#define C_W(b) (20480 + (b) * 40960)
#define C_HH   0
#define C_HL   33792
#define C_FC   67584
#define C_SS   104448
#define L_SMEM 104704

// ---------------- scratch ----------------------------------------------------
__device__ float g_F0[B_ROOT * 256];
__device__ float g_F1[R1 * 256];
__device__ __nv_bfloat16 g_whi[5 * 32768];
__device__ __nv_bfloat16 g_wlo[5 * 32768];
__device__ unsigned g_wflag;

// ---------------- helpers ----------------------------------------------------
__device__ __forceinline__ uint32_t smem_u32(const void* p) {
    uint32_t a;
    asm("{ .reg .u64 t; cvta.to.shared.u64 t, %1; cvt.u32.u64 %0, t; }"
        : "=r"(a) : "l"(p));
    return a;
}
__device__ __forceinline__ void split2(float a, float b, uint32_t& h, uint32_t& l) {
    __nv_bfloat16 ah = __float2bfloat16_rn(a), bh = __float2bfloat16_rn(b);
    __nv_bfloat16 al = __float2bfloat16_rn(a - __bfloat162float(ah));
    __nv_bfloat16 bl = __float2bfloat16_rn(b - __bfloat162float(bh));
    __nv_bfloat162 ph = __halves2bfloat162(ah, bh);
    __nv_bfloat162 pl = __halves2bfloat162(al, bl);
    h = *reinterpret_cast<uint32_t*>(&ph);
    l = *reinterpret_cast<uint32_t*>(&pl);
}
__device__ __forceinline__ void split8(const float* v, uint4& h4, uint4& l4) {
    uint32_t h[4], l[4];
#pragma unroll
    for (int i = 0; i < 4; ++i) split2(v[2 * i], v[2 * i + 1], h[i], l[i]);
    h4 = make_uint4(h[0], h[1], h[2], h[3]);
    l4 = make_uint4(l[0], l[1], l[2], l[3]);
}
__device__ __forceinline__ void mma16816(float* d, const uint32_t* a,
                                         uint32_t b0, uint32_t b1) {
    asm volatile(
        "mma.sync.aligned.m16n8k16.row.col.f32.bf16.bf16.f32 "
        "{%0,%1,%2,%3}, {%4,%5,%6,%7}, {%8,%9}, {%0,%1,%2,%3};"
        : "+f"(d[0]), "+f"(d[1]), "+f"(d[2]), "+f"(d[3])
        : "r"(a[0]), "r"(a[1]), "r"(a[2]), "r"(a[3]), "r"(b0), "r"(b1));
}
__device__ __forceinline__ void ldmx4(uint32_t* r, uint32_t a) {
    asm volatile("ldmatrix.sync.aligned.m8n8.x4.shared.b16 {%0,%1,%2,%3}, [%4];"
                 : "=r"(r[0]), "=r"(r[1]), "=r"(r[2]), "=r"(r[3]) : "r"(a));
}
__device__ __forceinline__ void cp16(uint32_t dst, const void* src) {
    asm volatile("cp.async.cg.shared.global [%0], [%1], 16;" :: "r"(dst), "l"(src));
}
#define CP_COMMIT() asm volatile("cp.async.commit_group;" ::: "memory")
#define CP_WAIT0()  asm volatile("cp.async.wait_group 0;"  ::: "memory")

// ---------------- layer-0 GEMM body (coalesced gathers) -------------------------
// GATHER: 0 = A[idx[m]], 1 = mean_{j<KF} A[idx[m*KF+j]]
// Lane->column map: thread (tid&3)=q4 owns float4 slots {q4+4q : q=0..3} of the
// row's 16-float4 chunk, so a quad's lanes read 64B CONTIGUOUS per instruction.
template <int GATHER, int KF>
__device__ __forceinline__ void
gemm_body(char* smem, const float* __restrict__ A, const int* __restrict__ idx,
          const __nv_bfloat16* __restrict__ w_hi, const __nv_bfloat16* __restrict__ w_lo,
          const float* __restrict__ bias,
          float* __restrict__ C, int ldc, int col_off, int m0)
{
    const uint32_t sb = smem_u32(smem);
    const int tid = threadIdx.x, lane = tid & 31, wid = tid >> 5;
    const int wm = wid >> 2, wn = wid & 3;
    const int lr = lane >> 2, lc = (lane & 3) * 2;
    const int g  = lane >> 3, lm = lane & 7;
    const int aro = ((g & 1) << 3) + lm, aco = (g >> 1) << 3;
    const int bro = ((g >> 1) << 3) + lm, bco = (g & 1) << 3;
    const int r  = tid >> 2, q4 = tid & 3;

    auto ISSUE_W = [&](int ch, int buf) {
        const int kb = ch * 64;
#pragma unroll
        for (int i = 0; i < 8; ++i) {
            int o = tid + i * 256;
            int plane = o >> 10, ix = o & 1023;
            int row = ix >> 3, c8 = (ix & 7) * 8;
            const __nv_bfloat16* src =
                (plane ? w_lo : w_hi) + (size_t)row * 256 + kb + c8;
            cp16(sb + GW(buf) + (plane ? 18432 : 0)
                 + (uint32_t)(row * RSA + c8) * 2, src);
        }
    };

    int rows[KF];
    if (GATHER == 0)      rows[0] = idx[m0 + r];
    else {
#pragma unroll
        for (int j = 0; j < KF; ++j) rows[j] = idx[(size_t)(m0 + r) * KF + j];
    }

    // v[q*4 + c] = float c of the thread's q-th float4 slot (slot idx q4+4q)
    float v[16];
    auto PREF = [&](int ch) {
        const int kb4 = ch * 16;     // float4 index of chunk start within row
        if (GATHER == 0) {
            const float4* p = (const float4*)A + (size_t)rows[0] * 64 + kb4 + q4;
            float4 t0 = __ldg(p), t1 = __ldg(p + 4), t2 = __ldg(p + 8), t3 = __ldg(p + 12);
            v[0]  = t0.x; v[1]  = t0.y; v[2]  = t0.z; v[3]  = t0.w;
            v[4]  = t1.x; v[5]  = t1.y; v[6]  = t1.z; v[7]  = t1.w;
            v[8]  = t2.x; v[9]  = t2.y; v[10] = t2.z; v[11] = t2.w;
            v[12] = t3.x; v[13] = t3.y; v[14] = t3.z; v[15] = t3.w;
        } else {
#pragma unroll
            for (int i = 0; i < 16; ++i) v[i] = 0.f;
#pragma unroll
            for (int h = 0; h < 2; ++h) {           // q pairs {0,1} then {2,3}
                float4 t[2 * KF];                   // independent loads -> high MLP
#pragma unroll
                for (int j = 0; j < KF; ++j) {
                    const float4* p = (const float4*)A + (size_t)rows[j] * 64
                                      + kb4 + q4 + h * 8;
                    t[j * 2]     = __ldg(p);        // slot q = 2h
                    t[j * 2 + 1] = __ldg(p + 4);    // slot q = 2h+1
                }
#pragma unroll
                for (int j = 0; j < KF; ++j)
#pragma unroll
                    for (int q = 0; q < 2; ++q) {
                        const float4 f = t[j * 2 + q];
                        const int o = (h * 2 + q) * 4;
                        v[o + 0] += f.x; v[o + 1] += f.y;
                        v[o + 2] += f.z; v[o + 3] += f.w;
                    }
            }
        }
    };
    auto STORE = [&](int buf) {
        const float s = 1.0f / (float)KF;
        char* base = smem + GA(buf);
#pragma unroll
        for (int q = 0; q < 4; ++q) {
            uint32_t h0, l0, h1, l1;
            split2(v[q * 4 + 0] * s, v[q * 4 + 1] * s, h0, l0);
            split2(v[q * 4 + 2] * s, v[q * 4 + 3] * s, h1, l1);
            const size_t off = ((size_t)r * RSA + (q4 + 4 * q) * 4) * 2;
            *(uint2*)(base + off)        = make_uint2(h0, h1);
            *(uint2*)(base + 9216 + off) = make_uint2(l0, l1);
        }
    };

    float d[2][4][4];
#pragma unroll
    for (int i = 0; i < 2; ++i)
#pragma unroll
        for (int j = 0; j < 4; ++j)
#pragma unroll
            for (int k = 0; k < 4; ++k) d[i][j][k] = 0.f;

    ISSUE_W(0, 0);
    CP_COMMIT();
    PREF(0);
    STORE(0);
    CP_WAIT0();
    __syncthreads();

#pragma unroll
    for (int ch = 0; ch < 4; ++ch) {
        const int cb = ch & 1, nb = cb ^ 1;
        if (ch < 3) {
            ISSUE_W(ch + 1, nb);
            CP_COMMIT();
            PREF(ch + 1);
        }
        const uint32_t aH = sb + GA(cb), aL = aH + 9216;
        const uint32_t wH = sb + GW(cb), wL = wH + 18432;
#pragma unroll
        for (int ks = 0; ks < 4; ++ks) {
            uint32_t ah[2][4], al[2][4];
#pragma unroll
            for (int mi = 0; mi < 2; ++mi) {
                uint32_t ad = (uint32_t)((wm * 32 + mi * 16 + aro) * RSA
                                         + ks * 16 + aco) * 2;
                ldmx4(ah[mi], aH + ad);
                ldmx4(al[mi], aL + ad);
            }
            uint32_t bh[4][2], bl[4][2];
#pragma unroll
            for (int nip = 0; nip < 2; ++nip) {
                uint32_t bd = (uint32_t)((wn * 32 + nip * 16 + bro) * RSA
                                         + ks * 16 + bco) * 2;
                uint32_t t4[4];
                ldmx4(t4, wH + bd);
                bh[2 * nip][0] = t4[0]; bh[2 * nip][1] = t4[1];
                bh[2 * nip + 1][0] = t4[2]; bh[2 * nip + 1][1] = t4[3];
                ldmx4(t4, wL + bd);
                bl[2 * nip][0] = t4[0]; bl[2 * nip][1] = t4[1];
                bl[2 * nip + 1][0] = t4[2]; bl[2 * nip + 1][1] = t4[3];
            }
#pragma unroll
            for (int ni = 0; ni < 4; ++ni)
#pragma unroll
                for (int mi = 0; mi < 2; ++mi) {
                    mma16816(d[mi][ni], ah[mi], bh[ni][0], bh[ni][1]);
                    mma16816(d[mi][ni], ah[mi], bl[ni][0], bl[ni][1]);
                    mma16816(d[mi][ni], al[mi], bh[ni][0], bh[ni][1]);
                }
        }
        if (ch < 3) {
            STORE(nb);
            CP_WAIT0();
        }
        __syncthreads();
    }

#pragma unroll
    for (int mi = 0; mi < 2; ++mi) {
        const int row = m0 + wm * 32 + mi * 16 + lr;
#pragma unroll
        for (int ni = 0; ni < 4; ++ni) {
            const int col = wn * 32 + ni * 8 + lc;
            const float b0 = __ldg(&bias[col]), b1 = __ldg(&bias[col + 1]);
            *(float2*)(C + (size_t)row * ldc + col_off + col) =
                make_float2(fmaxf(d[mi][ni][0] + b0, 0.f),
                            fmaxf(d[mi][ni][1] + b1, 0.f));
            *(float2*)(C + (size_t)(row + 8) * ldc + col_off + col) =
                make_float2(fmaxf(d[mi][ni][2] + b0, 0.f),
                            fmaxf(d[mi][ni][3] + b1, 0.f));
        }
    }
}

// ---------------- layer 0: fused weight-split + contiguous segments --------------
__global__ void __launch_bounds__(256, 2)
layer0_k(const float* __restrict__ emb,
         const int* __restrict__ nodeids, const int* __restrict__ neigh1,
         const int* __restrict__ neigh2,
         const float* __restrict__ ws0, const float* __restrict__ wn0,
         const float* __restrict__ ws1, const float* __restrict__ wn1,
         const float* __restrict__ fcw,
         __nv_bfloat16* __restrict__ whi_o, __nv_bfloat16* __restrict__ wlo_o,
         const __nv_bfloat16* __restrict__ whi, const __nv_bfloat16* __restrict__ wlo,
         const float* __restrict__ bs0, const float* __restrict__ bn0,
         float* __restrict__ F0, float* __restrict__ F1)
{
    extern __shared__ char smem[];
    const int bid = blockIdx.x;
    const int tid = threadIdx.x;

    if (bid < 8) {
        const float* src[5] = {ws0, wn0, ws1, wn1, fcw};
#pragma unroll
        for (int i = 0; i < 20; ++i) {
            int idx4 = bid * 5120 + i * 256 + tid;
            int base = idx4 * 4;
            float4 f = __ldg((const float4*)(src[base >> 15] + (base & 32767)));
            uint32_t h0, l0, h1, l1;
            split2(f.x, f.y, h0, l0);
            split2(f.z, f.w, h1, l1);
            *(uint2*)(whi_o + base) = make_uint2(h0, h1);
            *(uint2*)(wlo_o + base) = make_uint2(l0, l1);
        }
        __syncthreads();
        if (tid == 0) {
            unsigned old;
            asm volatile("atom.add.release.gpu.u32 %0, [%1], 1;"
                         : "=r"(old) : "l"(&g_wflag) : "memory");
        }
    }
    if (tid == 0) {
        unsigned val;
        do {
            asm volatile("ld.acquire.gpu.u32 %0, [%1];"
                         : "=r"(val) : "l"(&g_wflag) : "memory");
            if (val >= 8u) break;
            __nanosleep(64);
        } while (true);
    }
    __syncthreads();

    if (bid < 768) {
        gemm_body<1, 5>(smem, emb, neigh2, whi + 32768, wlo + 32768, bn0,
                        F1, 256, 128, bid * 64);
    } else if (bid < 1536) {
        gemm_body<0, 1>(smem, emb, neigh1, whi, wlo, bs0,
                        F1, 256, 0, (bid - 768) * 64);
    } else if (bid < 1792) {
        gemm_body<1, 3>(smem, emb, neigh1, whi + 32768, wlo + 32768, bn0,
                        F0, 256, 128, (bid - 1536) * 64);
    } else {
        gemm_body<0, 1>(smem, emb, nodeids, whi, wlo, bs0,
                        F0, 256, 0, (bid - 1792) * 64);
    }
}

// ---------------- fused layer1 + L2-norm + FC, 256 thr, 2 CTAs/SM ----------------
__global__ void __launch_bounds__(256, 2)
l1fc_k(const float* __restrict__ F0, const float* __restrict__ F1,
       const __nv_bfloat16* __restrict__ w1_hi, const __nv_bfloat16* __restrict__ w1_lo,
       const float* __restrict__ bS, const float* __restrict__ bN,
       const __nv_bfloat16* __restrict__ fc_hi, const __nv_bfloat16* __restrict__ fc_lo,
       const float* __restrict__ fcb, float* __restrict__ out)
{
    extern __shared__ char smem[];
    const uint32_t sb = smem_u32(smem);
    const int tid = threadIdx.x, lane = tid & 31, wid = tid >> 5;
    const int wm = wid >> 2, wn = wid & 3;
    const int lr = lane >> 2, lc = (lane & 3) * 2;
    const int g  = lane >> 3, lm = lane & 7;
    const int aro = ((g & 1) << 3) + lm, aco = (g >> 1) << 3;
    const int bro = ((g >> 1) << 3) + lm, bco = (g & 1) << 3;
    const int m0 = blockIdx.x * 64;

    if (blockIdx.x == 0 && tid == 0) {
        asm volatile("st.relaxed.gpu.u32 [%0], 0;" :: "l"(&g_wflag) : "memory");
    }

    const bool isSelf = tid < 128;
    const int lt = tid & 127;
    const int r = lt >> 1, cq = (lt & 1) * 16;

    auto ISSUE_W = [&](int ch, int buf) {
        const int kb = ch * 32;
#pragma unroll
        for (int i = 0; i < 8; ++i) {
            int o = tid + i * 256;
            int plane = o >> 10, ix = o & 1023;
            int row = ix >> 2, c8 = (ix & 3) * 8;
            const __nv_bfloat16* src =
                (plane ? w1_lo : w1_hi) + (size_t)row * 256 + kb + c8;
            cp16(sb + C_W(buf) + (plane ? 20480 : 0)
                 + (uint32_t)(row * RSC + c8) * 2, src);
        }
    };

    float v[16];
    auto PREF = [&](int ch) {
        const int kb = ch * 32;
        if (isSelf) {
            const float4* p = (const float4*)(F0 + (size_t)(m0 + r) * 256 + kb + cq);
            float4 t0 = __ldg(p), t1 = __ldg(p + 1), t2 = __ldg(p + 2), t3 = __ldg(p + 3);
            v[0]  = t0.x; v[1]  = t0.y; v[2]  = t0.z; v[3]  = t0.w;
            v[4]  = t1.x; v[5]  = t1.y; v[6]  = t1.z; v[7]  = t1.w;
            v[8]  = t2.x; v[9]  = t2.y; v[10] = t2.z; v[11] = t2.w;
            v[12] = t3.x; v[13] = t3.y; v[14] = t3.z; v[15] = t3.w;
        } else {
            float4 t[12];
#pragma unroll
            for (int j = 0; j < 3; ++j) {
                const float4* p = (const float4*)(F1
                    + (size_t)((m0 + r) * 3 + j) * 256 + kb + cq);
#pragma unroll
                for (int q = 0; q < 4; ++q) t[j * 4 + q] = __ldg(p + q);
            }
#pragma unroll
            for (int i = 0; i < 16; ++i) v[i] = 0.f;
#pragma unroll
            for (int j = 0; j < 3; ++j)
#pragma unroll
                for (int q = 0; q < 4; ++q) {
                    const float4 f = t[j * 4 + q];
                    v[q * 4 + 0] += f.x; v[q * 4 + 1] += f.y;
                    v[q * 4 + 2] += f.z; v[q * 4 + 3] += f.w;
                }
#pragma unroll
            for (int i = 0; i < 16; ++i) v[i] *= (1.0f / 3.0f);
        }
    };
    auto STORE = [&]() {
        uint4 h0, l0, h1, l1;
        split8(v, h0, l0);
        split8(v + 8, h1, l1);
        char* base = smem + (isSelf ? C_ASH : C_ANH) + (size_t)(r * RSC + cq) * 2;
        *(uint4*)(base)             = h0;
        *(uint4*)(base + 16)        = h1;
        *(uint4*)(base + 5120)      = l0;
        *(uint4*)(base + 5120 + 16) = l1;
    };

    float d[2][8][4];
#pragma unroll
    for (int i = 0; i < 2; ++i)
#pragma unroll
        for (int j = 0; j < 8; ++j)
#pragma unroll
            for (int k = 0; k < 4; ++k) d[i][j][k] = 0.f;

    ISSUE_W(0, 0);
    CP_COMMIT();
    PREF(0);
    STORE();
    CP_WAIT0();
    __syncthreads();

#pragma unroll
    for (int ch = 0; ch < 8; ++ch) {
        const int cb = ch & 1, nb = cb ^ 1;
        if (ch < 7) {
            ISSUE_W(ch + 1, nb);
            CP_COMMIT();
            PREF(ch + 1);
        }
        const uint32_t aH = sb + (wn < 2 ? C_ASH : C_ANH);
        const uint32_t aL = aH + 5120;
        const uint32_t wH = sb + C_W(cb), wL = wH + 20480;
#pragma unroll
        for (int ks = 0; ks < 2; ++ks) {
            uint32_t ah[2][4], al[2][4];
#pragma unroll
            for (int mi = 0; mi < 2; ++mi) {
                uint32_t ad = (uint32_t)((wm * 32 + mi * 16 + aro) * RSC
                                         + ks * 16 + aco) * 2;
                ldmx4(ah[mi], aH + ad);
                ldmx4(al[mi], aL + ad);
            }
#pragma unroll
            for (int nip = 0; nip < 4; ++nip) {
                uint32_t bd = (uint32_t)((wn * 64 + nip * 16 + bro) * RSC
                                         + ks * 16 + bco) * 2;
                uint32_t th[4], tl[4];
                ldmx4(th, wH + bd);
                ldmx4(tl, wL + bd);
#pragma unroll
                for (int sub = 0; sub < 2; ++sub) {
                    const int ni = 2 * nip + sub;
#pragma unroll
                    for (int mi = 0; mi < 2; ++mi) {
                        mma16816(d[mi][ni], ah[mi], th[2 * sub], th[2 * sub + 1]);
                        mma16816(d[mi][ni], ah[mi], tl[2 * sub], tl[2 * sub + 1]);
                        mma16816(d[mi][ni], al[mi], th[2 * sub], th[2 * sub + 1]);
                    }
                }
            }
        }
        __syncthreads();
        if (ch < 7) {
            STORE();
            CP_WAIT0();
            __syncthreads();
        }
    }

    auto ISSUE_FC = [&](int ch) {
        const int kb = ch * 64;
#pragma unroll
        for (int i = 0; i < 8; ++i) {
            int o = tid + i * 256;
            int plane = o >> 10, ix = o & 1023;
            int row = ix >> 3, c8 = (ix & 7) * 8;
            const __nv_bfloat16* src = (plane ? fc_lo : fc_hi)
                                     + (size_t)row * 256 + kb + c8;
            cp16(sb + C_FC + (plane ? 18432 : 0)
                 + (uint32_t)(row * RSA + c8) * 2, src);
        }
    };
    ISSUE_FC(0);
    CP_COMMIT();

    float* ss = (float*)(smem + C_SS);
    if (tid < 64) ss[tid] = 0.f;
    __syncthreads();

#pragma unroll
    for (int mi = 0; mi < 2; ++mi) {
        const int r0 = wm * 32 + mi * 16 + lr;
        float s0 = 0.f, s1 = 0.f;
#pragma unroll
        for (int ni = 0; ni < 8; ++ni) {
            const int col = wn * 64 + ni * 8 + lc;
            const float b0 = (col < 128) ? bS[col] : bN[col - 128];
            const float b1 = (col + 1 < 128) ? bS[col + 1] : bN[col - 127];
            d[mi][ni][0] = fmaxf(d[mi][ni][0] + b0, 0.f);
            d[mi][ni][1] = fmaxf(d[mi][ni][1] + b1, 0.f);
            d[mi][ni][2] = fmaxf(d[mi][ni][2] + b0, 0.f);
            d[mi][ni][3] = fmaxf(d[mi][ni][3] + b1, 0.f);
            s0 += d[mi][ni][0] * d[mi][ni][0] + d[mi][ni][1] * d[mi][ni][1];
            s1 += d[mi][ni][2] * d[mi][ni][2] + d[mi][ni][3] * d[mi][ni][3];
        }
        s0 += __shfl_xor_sync(0xffffffffu, s0, 1);
        s0 += __shfl_xor_sync(0xffffffffu, s0, 2);
        s1 += __shfl_xor_sync(0xffffffffu, s1, 1);
        s1 += __shfl_xor_sync(0xffffffffu, s1, 2);
        if ((lane & 3) == 0) {
            atomicAdd(&ss[r0], s0);
            atomicAdd(&ss[r0 + 8], s1);
        }
    }
    __syncthreads();

#pragma unroll
    for (int mi = 0; mi < 2; ++mi) {
        const int r0 = wm * 32 + mi * 16 + lr;
        const float sc0 = 1.0f / fmaxf(sqrtf(ss[r0]), 1e-12f);
        const float sc1 = 1.0f / fmaxf(sqrtf(ss[r0 + 8]), 1e-12f);
#pragma unroll
        for (int ni = 0; ni < 8; ++ni) {
            const int col = wn * 64 + ni * 8 + lc;
            uint32_t h, l;
            split2(d[mi][ni][0] * sc0, d[mi][ni][1] * sc0, h, l);
            *(uint32_t*)(smem + C_HH + (size_t)(r0 * RSH + col) * 2) = h;
            *(uint32_t*)(smem + C_HL + (size_t)(r0 * RSH + col) * 2) = l;
            split2(d[mi][ni][2] * sc1, d[mi][ni][3] * sc1, h, l);
            *(uint32_t*)(smem + C_HH + (size_t)((r0 + 8) * RSH + col) * 2) = h;
            *(uint32_t*)(smem + C_HL + (size_t)((r0 + 8) * RSH + col) * 2) = l;
        }
    }
    CP_WAIT0();
    __syncthreads();

    float e[2][4][4];
#pragma unroll
    for (int i = 0; i < 2; ++i)
#pragma unroll
        for (int j = 0; j < 4; ++j)
#pragma unroll
            for (int k = 0; k < 4; ++k) e[i][j][k] = 0.f;

#pragma unroll
    for (int ch = 0; ch < 4; ++ch) {
        const int kb = ch * 64;
        const uint32_t fH = sb + C_FC, fL = fH + 18432;
#pragma unroll
        for (int ks = 0; ks < 4; ++ks) {
            uint32_t ah[2][4], al[2][4];
#pragma unroll
            for (int mi = 0; mi < 2; ++mi) {
                uint32_t ad = (uint32_t)((wm * 32 + mi * 16 + aro) * RSH
                                         + kb + ks * 16 + aco) * 2;
                ldmx4(ah[mi], sb + C_HH + ad);
                ldmx4(al[mi], sb + C_HL + ad);
            }
#pragma unroll
            for (int nip = 0; nip < 2; ++nip) {
                uint32_t bd = (uint32_t)((wn * 32 + nip * 16 + bro) * RSA
                                         + ks * 16 + bco) * 2;
                uint32_t th[4], tl[4];
                ldmx4(th, fH + bd);
                ldmx4(tl, fL + bd);
#pragma unroll
                for (int sub = 0; sub < 2; ++sub) {
                    const int ni = 2 * nip + sub;
#pragma unroll
                    for (int mi = 0; mi < 2; ++mi) {
                        mma16816(e[mi][ni], ah[mi], th[2 * sub], th[2 * sub + 1]);
                        mma16816(e[mi][ni], ah[mi], tl[2 * sub], tl[2 * sub + 1]);
                        mma16816(e[mi][ni], al[mi], th[2 * sub], th[2 * sub + 1]);
                    }
                }
            }
        }
        if (ch < 3) {
            __syncthreads();
            ISSUE_FC(ch + 1);
            CP_COMMIT();
            CP_WAIT0();
            __syncthreads();
        }
    }

#pragma unroll
    for (int mi = 0; mi < 2; ++mi) {
        const int row = m0 + wm * 32 + mi * 16 + lr;
#pragma unroll
        for (int ni = 0; ni < 4; ++ni) {
            const int col = wn * 32 + ni * 8 + lc;
            const float b0 = __ldg(&fcb[col]), b1 = __ldg(&fcb[col + 1]);
            *(float2*)(out + (size_t)row * 128 + col) =
                make_float2(e[mi][ni][0] + b0, e[mi][ni][1] + b1);
            *(float2*)(out + (size_t)(row + 8) * 128 + col) =
                make_float2(e[mi][ni][2] + b0, e[mi][ni][3] + b1);
        }
    }
}

// ---------------------------------------------------------------------------
extern "C" void kernel_launch(void* const* d_in, const int* in_sizes, int n_in,
                              void* d_out, int out_size)
{
    const float* emb      = (const float*)d_in[0];
    const float* w_self0  = (const float*)d_in[1];
    const float* b_self0  = (const float*)d_in[2];
    const float* w_neigh0 = (const float*)d_in[3];
    const float* b_neigh0 = (const float*)d_in[4];
    const float* w_self1  = (const float*)d_in[5];
    const float* b_self1  = (const float*)d_in[6];
    const float* w_neigh1 = (const float*)d_in[7];
    const float* b_neigh1 = (const float*)d_in[8];
    const float* fc_w     = (const float*)d_in[9];
    const float* fc_b     = (const float*)d_in[10];
    const int*   nodeids  = (const int*)d_in[11];
    const int*   neigh1   = (const int*)d_in[12];
    const int*   neigh2   = (const int*)d_in[13];
    float*       out      = (float*)d_out;

    __nv_bfloat16 *WHI, *WLO;
    float *F0, *F1;
    cudaGetSymbolAddress((void**)&WHI, g_whi);
    cudaGetSymbolAddress((void**)&WLO, g_wlo);
    cudaGetSymbolAddress((void**)&F0, g_F0);
    cudaGetSymbolAddress((void**)&F1, g_F1);

    cudaFuncSetAttribute(layer0_k, cudaFuncAttributeMaxDynamicSharedMemorySize, G_SMEM);
    cudaFuncSetAttribute(l1fc_k,   cudaFuncAttributeMaxDynamicSharedMemorySize, L_SMEM);

    layer0_k<<<2048, 256, G_SMEM>>>(emb, nodeids, neigh1, neigh2,
                                    w_self0, w_neigh0, w_self1, w_neigh1, fc_w,
                                    WHI, WLO, WHI, WLO,
                                    b_self0, b_neigh0, F0, F1);

    l1fc_k<<<B_ROOT / 64, 256, L_SMEM>>>(F0, F1,
                                         WHI + 65536, WLO + 65536,
                                         b_self1, b_neigh1,
                                         WHI + 131072, WLO + 131072,
                                         fc_b, out);
}

// round 16
// speedup vs baseline: 1.1734x; 1.0115x over previous
#include <cuda_runtime.h>
#include <cuda_bf16.h>
#include <cstdint>

// ---------------------------------------------------------------------------
// GraphSAGE, mma.sync bf16 hi/lo (3-product fp32-accurate). Two launches:
// layer0_k: weight pre-split fused (8 converter CTAs + acquire flag); 4 GEMM
//   segments CONTIGUOUS; gemm_body = 256 thr, M64 x N128, K=256 in 4 chunks,
//   2 CTAs/SM; gather lanes read interleaved float4s (coalesced 64B/quad).
// l1fc_k: 256 thr, 2 CTAs/SM; stage1 M64 x N256 layer-1 (k32 chunks), row
//   L2-norm, stage2 FC — fused. NEW: coalesced interleaved loaders (32B
//   contiguous per row pair per instr) like layer0.
// ---------------------------------------------------------------------------

#define B_ROOT 16384
#define R1     49152
#define RSA    72            // k64 tile row stride (bf16 elems)
#define RSC    40            // k32 tile row stride (bf16 elems)
#define RSH    264           // h row stride

// layer0 smem (bytes)
#define GA(b)  ((b) * 18432)                 // A: hi +0, lo +9216
#define GW(b)  (36864 + (b) * 36864)         // W: hi +0, lo +18432
#define G_SMEM 110592
// l1fc smem (bytes)
#define C_ASH  0
#define C_ASL  5120
#define C_ANH  10240
#define C_ANL  15360
#define C_W(b) (20480 + (b) * 40960)
#define C_HH   0
#define C_HL   33792
#define C_FC   67584
#define C_SS   104448
#define L_SMEM 104704

// ---------------- scratch ----------------------------------------------------
__device__ float g_F0[B_ROOT * 256];
__device__ float g_F1[R1 * 256];
__device__ __nv_bfloat16 g_whi[5 * 32768];
__device__ __nv_bfloat16 g_wlo[5 * 32768];
__device__ unsigned g_wflag;

// ---------------- helpers ----------------------------------------------------
__device__ __forceinline__ uint32_t smem_u32(const void* p) {
    uint32_t a;
    asm("{ .reg .u64 t; cvta.to.shared.u64 t, %1; cvt.u32.u64 %0, t; }"
        : "=r"(a) : "l"(p));
    return a;
}
__device__ __forceinline__ void split2(float a, float b, uint32_t& h, uint32_t& l) {
    __nv_bfloat16 ah = __float2bfloat16_rn(a), bh = __float2bfloat16_rn(b);
    __nv_bfloat16 al = __float2bfloat16_rn(a - __bfloat162float(ah));
    __nv_bfloat16 bl = __float2bfloat16_rn(b - __bfloat162float(bh));
    __nv_bfloat162 ph = __halves2bfloat162(ah, bh);
    __nv_bfloat162 pl = __halves2bfloat162(al, bl);
    h = *reinterpret_cast<uint32_t*>(&ph);
    l = *reinterpret_cast<uint32_t*>(&pl);
}
__device__ __forceinline__ void mma16816(float* d, const uint32_t* a,
                                         uint32_t b0, uint32_t b1) {
    asm volatile(
        "mma.sync.aligned.m16n8k16.row.col.f32.bf16.bf16.f32 "
        "{%0,%1,%2,%3}, {%4,%5,%6,%7}, {%8,%9}, {%0,%1,%2,%3};"
        : "+f"(d[0]), "+f"(d[1]), "+f"(d[2]), "+f"(d[3])
        : "r"(a[0]), "r"(a[1]), "r"(a[2]), "r"(a[3]), "r"(b0), "r"(b1));
}
__device__ __forceinline__ void ldmx4(uint32_t* r, uint32_t a) {
    asm volatile("ldmatrix.sync.aligned.m8n8.x4.shared.b16 {%0,%1,%2,%3}, [%4];"
                 : "=r"(r[0]), "=r"(r[1]), "=r"(r[2]), "=r"(r[3]) : "r"(a));
}
__device__ __forceinline__ void cp16(uint32_t dst, const void* src) {
    asm volatile("cp.async.cg.shared.global [%0], [%1], 16;" :: "r"(dst), "l"(src));
}
#define CP_COMMIT() asm volatile("cp.async.commit_group;" ::: "memory")
#define CP_WAIT0()  asm volatile("cp.async.wait_group 0;"  ::: "memory")

// ---------------- layer-0 GEMM body (R15, proven) -------------------------------
template <int GATHER, int KF>
__device__ __forceinline__ void
gemm_body(char* smem, const float* __restrict__ A, const int* __restrict__ idx,
          const __nv_bfloat16* __restrict__ w_hi, const __nv_bfloat16* __restrict__ w_lo,
          const float* __restrict__ bias,
          float* __restrict__ C, int ldc, int col_off, int m0)
{
    const uint32_t sb = smem_u32(smem);
    const int tid = threadIdx.x, lane = tid & 31, wid = tid >> 5;
    const int wm = wid >> 2, wn = wid & 3;
    const int lr = lane >> 2, lc = (lane & 3) * 2;
    const int g  = lane >> 3, lm = lane & 7;
    const int aro = ((g & 1) << 3) + lm, aco = (g >> 1) << 3;
    const int bro = ((g >> 1) << 3) + lm, bco = (g & 1) << 3;
    const int r  = tid >> 2, q4 = tid & 3;

    auto ISSUE_W = [&](int ch, int buf) {
        const int kb = ch * 64;
#pragma unroll
        for (int i = 0; i < 8; ++i) {
            int o = tid + i * 256;
            int plane = o >> 10, ix = o & 1023;
            int row = ix >> 3, c8 = (ix & 7) * 8;
            const __nv_bfloat16* src =
                (plane ? w_lo : w_hi) + (size_t)row * 256 + kb + c8;
            cp16(sb + GW(buf) + (plane ? 18432 : 0)
                 + (uint32_t)(row * RSA + c8) * 2, src);
        }
    };

    int rows[KF];
    if (GATHER == 0)      rows[0] = idx[m0 + r];
    else {
#pragma unroll
        for (int j = 0; j < KF; ++j) rows[j] = idx[(size_t)(m0 + r) * KF + j];
    }

    float v[16];
    auto PREF = [&](int ch) {
        const int kb4 = ch * 16;
        if (GATHER == 0) {
            const float4* p = (const float4*)A + (size_t)rows[0] * 64 + kb4 + q4;
            float4 t0 = __ldg(p), t1 = __ldg(p + 4), t2 = __ldg(p + 8), t3 = __ldg(p + 12);
            v[0]  = t0.x; v[1]  = t0.y; v[2]  = t0.z; v[3]  = t0.w;
            v[4]  = t1.x; v[5]  = t1.y; v[6]  = t1.z; v[7]  = t1.w;
            v[8]  = t2.x; v[9]  = t2.y; v[10] = t2.z; v[11] = t2.w;
            v[12] = t3.x; v[13] = t3.y; v[14] = t3.z; v[15] = t3.w;
        } else {
#pragma unroll
            for (int i = 0; i < 16; ++i) v[i] = 0.f;
#pragma unroll
            for (int h = 0; h < 2; ++h) {
                float4 t[2 * KF];
#pragma unroll
                for (int j = 0; j < KF; ++j) {
                    const float4* p = (const float4*)A + (size_t)rows[j] * 64
                                      + kb4 + q4 + h * 8;
                    t[j * 2]     = __ldg(p);
                    t[j * 2 + 1] = __ldg(p + 4);
                }
#pragma unroll
                for (int j = 0; j < KF; ++j)
#pragma unroll
                    for (int q = 0; q < 2; ++q) {
                        const float4 f = t[j * 2 + q];
                        const int o = (h * 2 + q) * 4;
                        v[o + 0] += f.x; v[o + 1] += f.y;
                        v[o + 2] += f.z; v[o + 3] += f.w;
                    }
            }
        }
    };
    auto STORE = [&](int buf) {
        const float s = 1.0f / (float)KF;
        char* base = smem + GA(buf);
#pragma unroll
        for (int q = 0; q < 4; ++q) {
            uint32_t h0, l0, h1, l1;
            split2(v[q * 4 + 0] * s, v[q * 4 + 1] * s, h0, l0);
            split2(v[q * 4 + 2] * s, v[q * 4 + 3] * s, h1, l1);
            const size_t off = ((size_t)r * RSA + (q4 + 4 * q) * 4) * 2;
            *(uint2*)(base + off)        = make_uint2(h0, h1);
            *(uint2*)(base + 9216 + off) = make_uint2(l0, l1);
        }
    };

    float d[2][4][4];
#pragma unroll
    for (int i = 0; i < 2; ++i)
#pragma unroll
        for (int j = 0; j < 4; ++j)
#pragma unroll
            for (int k = 0; k < 4; ++k) d[i][j][k] = 0.f;

    ISSUE_W(0, 0);
    CP_COMMIT();
    PREF(0);
    STORE(0);
    CP_WAIT0();
    __syncthreads();

#pragma unroll
    for (int ch = 0; ch < 4; ++ch) {
        const int cb = ch & 1, nb = cb ^ 1;
        if (ch < 3) {
            ISSUE_W(ch + 1, nb);
            CP_COMMIT();
            PREF(ch + 1);
        }
        const uint32_t aH = sb + GA(cb), aL = aH + 9216;
        const uint32_t wH = sb + GW(cb), wL = wH + 18432;
#pragma unroll
        for (int ks = 0; ks < 4; ++ks) {
            uint32_t ah[2][4], al[2][4];
#pragma unroll
            for (int mi = 0; mi < 2; ++mi) {
                uint32_t ad = (uint32_t)((wm * 32 + mi * 16 + aro) * RSA
                                         + ks * 16 + aco) * 2;
                ldmx4(ah[mi], aH + ad);
                ldmx4(al[mi], aL + ad);
            }
            uint32_t bh[4][2], bl[4][2];
#pragma unroll
            for (int nip = 0; nip < 2; ++nip) {
                uint32_t bd = (uint32_t)((wn * 32 + nip * 16 + bro) * RSA
                                         + ks * 16 + bco) * 2;
                uint32_t t4[4];
                ldmx4(t4, wH + bd);
                bh[2 * nip][0] = t4[0]; bh[2 * nip][1] = t4[1];
                bh[2 * nip + 1][0] = t4[2]; bh[2 * nip + 1][1] = t4[3];
                ldmx4(t4, wL + bd);
                bl[2 * nip][0] = t4[0]; bl[2 * nip][1] = t4[1];
                bl[2 * nip + 1][0] = t4[2]; bl[2 * nip + 1][1] = t4[3];
            }
#pragma unroll
            for (int ni = 0; ni < 4; ++ni)
#pragma unroll
                for (int mi = 0; mi < 2; ++mi) {
                    mma16816(d[mi][ni], ah[mi], bh[ni][0], bh[ni][1]);
                    mma16816(d[mi][ni], ah[mi], bl[ni][0], bl[ni][1]);
                    mma16816(d[mi][ni], al[mi], bh[ni][0], bh[ni][1]);
                }
        }
        if (ch < 3) {
            STORE(nb);
            CP_WAIT0();
        }
        __syncthreads();
    }

#pragma unroll
    for (int mi = 0; mi < 2; ++mi) {
        const int row = m0 + wm * 32 + mi * 16 + lr;
#pragma unroll
        for (int ni = 0; ni < 4; ++ni) {
            const int col = wn * 32 + ni * 8 + lc;
            const float b0 = __ldg(&bias[col]), b1 = __ldg(&bias[col + 1]);
            *(float2*)(C + (size_t)row * ldc + col_off + col) =
                make_float2(fmaxf(d[mi][ni][0] + b0, 0.f),
                            fmaxf(d[mi][ni][1] + b1, 0.f));
            *(float2*)(C + (size_t)(row + 8) * ldc + col_off + col) =
                make_float2(fmaxf(d[mi][ni][2] + b0, 0.f),
                            fmaxf(d[mi][ni][3] + b1, 0.f));
        }
    }
}

// ---------------- layer 0: fused weight-split + contiguous segments --------------
__global__ void __launch_bounds__(256, 2)
layer0_k(const float* __restrict__ emb,
         const int* __restrict__ nodeids, const int* __restrict__ neigh1,
         const int* __restrict__ neigh2,
         const float* __restrict__ ws0, const float* __restrict__ wn0,
         const float* __restrict__ ws1, const float* __restrict__ wn1,
         const float* __restrict__ fcw,
         __nv_bfloat16* __restrict__ whi_o, __nv_bfloat16* __restrict__ wlo_o,
         const __nv_bfloat16* __restrict__ whi, const __nv_bfloat16* __restrict__ wlo,
         const float* __restrict__ bs0, const float* __restrict__ bn0,
         float* __restrict__ F0, float* __restrict__ F1)
{
    extern __shared__ char smem[];
    const int bid = blockIdx.x;
    const int tid = threadIdx.x;

    if (bid < 8) {
        const float* src[5] = {ws0, wn0, ws1, wn1, fcw};
#pragma unroll
        for (int i = 0; i < 20; ++i) {
            int idx4 = bid * 5120 + i * 256 + tid;
            int base = idx4 * 4;
            float4 f = __ldg((const float4*)(src[base >> 15] + (base & 32767)));
            uint32_t h0, l0, h1, l1;
            split2(f.x, f.y, h0, l0);
            split2(f.z, f.w, h1, l1);
            *(uint2*)(whi_o + base) = make_uint2(h0, h1);
            *(uint2*)(wlo_o + base) = make_uint2(l0, l1);
        }
        __syncthreads();
        if (tid == 0) {
            unsigned old;
            asm volatile("atom.add.release.gpu.u32 %0, [%1], 1;"
                         : "=r"(old) : "l"(&g_wflag) : "memory");
        }
    }
    if (tid == 0) {
        unsigned val;
        do {
            asm volatile("ld.acquire.gpu.u32 %0, [%1];"
                         : "=r"(val) : "l"(&g_wflag) : "memory");
            if (val >= 8u) break;
            __nanosleep(64);
        } while (true);
    }
    __syncthreads();

    if (bid < 768) {
        gemm_body<1, 5>(smem, emb, neigh2, whi + 32768, wlo + 32768, bn0,
                        F1, 256, 128, bid * 64);
    } else if (bid < 1536) {
        gemm_body<0, 1>(smem, emb, neigh1, whi, wlo, bs0,
                        F1, 256, 0, (bid - 768) * 64);
    } else if (bid < 1792) {
        gemm_body<1, 3>(smem, emb, neigh1, whi + 32768, wlo + 32768, bn0,
                        F0, 256, 128, (bid - 1536) * 64);
    } else {
        gemm_body<0, 1>(smem, emb, nodeids, whi, wlo, bs0,
                        F0, 256, 0, (bid - 1792) * 64);
    }
}

// ---------------- fused layer1 + L2-norm + FC, 256 thr, 2 CTAs/SM ----------------
// Loaders use interleaved slot map: thread q2=lt&1 owns float4 slots {q2+2q}
// of the row's 8-slot k32 chunk -> 32B contiguous per row pair per LDG.
__global__ void __launch_bounds__(256, 2)
l1fc_k(const float* __restrict__ F0, const float* __restrict__ F1,
       const __nv_bfloat16* __restrict__ w1_hi, const __nv_bfloat16* __restrict__ w1_lo,
       const float* __restrict__ bS, const float* __restrict__ bN,
       const __nv_bfloat16* __restrict__ fc_hi, const __nv_bfloat16* __restrict__ fc_lo,
       const float* __restrict__ fcb, float* __restrict__ out)
{
    extern __shared__ char smem[];
    const uint32_t sb = smem_u32(smem);
    const int tid = threadIdx.x, lane = tid & 31, wid = tid >> 5;
    const int wm = wid >> 2, wn = wid & 3;
    const int lr = lane >> 2, lc = (lane & 3) * 2;
    const int g  = lane >> 3, lm = lane & 7;
    const int aro = ((g & 1) << 3) + lm, aco = (g >> 1) << 3;
    const int bro = ((g >> 1) << 3) + lm, bco = (g & 1) << 3;
    const int m0 = blockIdx.x * 64;

    if (blockIdx.x == 0 && tid == 0) {
        asm volatile("st.relaxed.gpu.u32 [%0], 0;" :: "l"(&g_wflag) : "memory");
    }

    const bool isSelf = tid < 128;
    const int lt = tid & 127;
    const int r = lt >> 1, q2 = lt & 1;

    auto ISSUE_W = [&](int ch, int buf) {
        const int kb = ch * 32;
#pragma unroll
        for (int i = 0; i < 8; ++i) {
            int o = tid + i * 256;
            int plane = o >> 10, ix = o & 1023;
            int row = ix >> 2, c8 = (ix & 3) * 8;
            const __nv_bfloat16* src =
                (plane ? w1_lo : w1_hi) + (size_t)row * 256 + kb + c8;
            cp16(sb + C_W(buf) + (plane ? 20480 : 0)
                 + (uint32_t)(row * RSC + c8) * 2, src);
        }
    };

    // v[q*4 + c] = float c of slot (q2 + 2q) of this row's 8-float4 chunk
    float v[16];
    auto PREF = [&](int ch) {
        const int kb4 = ch * 8;       // float4 index of chunk start within row
        if (isSelf) {
            const float4* p = (const float4*)F0 + (size_t)(m0 + r) * 64 + kb4 + q2;
            float4 t0 = __ldg(p), t1 = __ldg(p + 2), t2 = __ldg(p + 4), t3 = __ldg(p + 6);
            v[0]  = t0.x; v[1]  = t0.y; v[2]  = t0.z; v[3]  = t0.w;
            v[4]  = t1.x; v[5]  = t1.y; v[6]  = t1.z; v[7]  = t1.w;
            v[8]  = t2.x; v[9]  = t2.y; v[10] = t2.z; v[11] = t2.w;
            v[12] = t3.x; v[13] = t3.y; v[14] = t3.z; v[15] = t3.w;
        } else {
            float4 t[12];
#pragma unroll
            for (int j = 0; j < 3; ++j) {
                const float4* p = (const float4*)F1
                    + (size_t)((m0 + r) * 3 + j) * 64 + kb4 + q2;
                t[j * 4 + 0] = __ldg(p);
                t[j * 4 + 1] = __ldg(p + 2);
                t[j * 4 + 2] = __ldg(p + 4);
                t[j * 4 + 3] = __ldg(p + 6);
            }
#pragma unroll
            for (int i = 0; i < 16; ++i) v[i] = 0.f;
#pragma unroll
            for (int j = 0; j < 3; ++j)
#pragma unroll
                for (int q = 0; q < 4; ++q) {
                    const float4 f = t[j * 4 + q];
                    v[q * 4 + 0] += f.x; v[q * 4 + 1] += f.y;
                    v[q * 4 + 2] += f.z; v[q * 4 + 3] += f.w;
                }
#pragma unroll
            for (int i = 0; i < 16; ++i) v[i] *= (1.0f / 3.0f);
        }
    };
    auto STORE = [&]() {
        char* base = smem + (isSelf ? C_ASH : C_ANH);
#pragma unroll
        for (int q = 0; q < 4; ++q) {
            uint32_t h0, l0, h1, l1;
            split2(v[q * 4 + 0], v[q * 4 + 1], h0, l0);
            split2(v[q * 4 + 2], v[q * 4 + 3], h1, l1);
            const size_t off = ((size_t)r * RSC + (q2 + 2 * q) * 4) * 2;
            *(uint2*)(base + off)        = make_uint2(h0, h1);
            *(uint2*)(base + 5120 + off) = make_uint2(l0, l1);
        }
    };

    float d[2][8][4];
#pragma unroll
    for (int i = 0; i < 2; ++i)
#pragma unroll
        for (int j = 0; j < 8; ++j)
#pragma unroll
            for (int k = 0; k < 4; ++k) d[i][j][k] = 0.f;

    ISSUE_W(0, 0);
    CP_COMMIT();
    PREF(0);
    STORE();
    CP_WAIT0();
    __syncthreads();

#pragma unroll
    for (int ch = 0; ch < 8; ++ch) {
        const int cb = ch & 1, nb = cb ^ 1;
        if (ch < 7) {
            ISSUE_W(ch + 1, nb);
            CP_COMMIT();
            PREF(ch + 1);
        }
        const uint32_t aH = sb + (wn < 2 ? C_ASH : C_ANH);
        const uint32_t aL = aH + 5120;
        const uint32_t wH = sb + C_W(cb), wL = wH + 20480;
#pragma unroll
        for (int ks = 0; ks < 2; ++ks) {
            uint32_t ah[2][4], al[2][4];
#pragma unroll
            for (int mi = 0; mi < 2; ++mi) {
                uint32_t ad = (uint32_t)((wm * 32 + mi * 16 + aro) * RSC
                                         + ks * 16 + aco) * 2;
                ldmx4(ah[mi], aH + ad);
                ldmx4(al[mi], aL + ad);
            }
#pragma unroll
            for (int nip = 0; nip < 4; ++nip) {
                uint32_t bd = (uint32_t)((wn * 64 + nip * 16 + bro) * RSC
                                         + ks * 16 + bco) * 2;
                uint32_t th[4], tl[4];
                ldmx4(th, wH + bd);
                ldmx4(tl, wL + bd);
#pragma unroll
                for (int sub = 0; sub < 2; ++sub) {
                    const int ni = 2 * nip + sub;
#pragma unroll
                    for (int mi = 0; mi < 2; ++mi) {
                        mma16816(d[mi][ni], ah[mi], th[2 * sub], th[2 * sub + 1]);
                        mma16816(d[mi][ni], ah[mi], tl[2 * sub], tl[2 * sub + 1]);
                        mma16816(d[mi][ni], al[mi], th[2 * sub], th[2 * sub + 1]);
                    }
                }
            }
        }
        __syncthreads();
        if (ch < 7) {
            STORE();
            CP_WAIT0();
            __syncthreads();
        }
    }

    auto ISSUE_FC = [&](int ch) {
        const int kb = ch * 64;
#pragma unroll
        for (int i = 0; i < 8; ++i) {
            int o = tid + i * 256;
            int plane = o >> 10, ix = o & 1023;
            int row = ix >> 3, c8 = (ix & 7) * 8;
            const __nv_bfloat16* src = (plane ? fc_lo : fc_hi)
                                     + (size_t)row * 256 + kb + c8;
            cp16(sb + C_FC + (plane ? 18432 : 0)
                 + (uint32_t)(row * RSA + c8) * 2, src);
        }
    };
    ISSUE_FC(0);
    CP_COMMIT();

    float* ss = (float*)(smem + C_SS);
    if (tid < 64) ss[tid] = 0.f;
    __syncthreads();

#pragma unroll
    for (int mi = 0; mi < 2; ++mi) {
        const int r0 = wm * 32 + mi * 16 + lr;
        float s0 = 0.f, s1 = 0.f;
#pragma unroll
        for (int ni = 0; ni < 8; ++ni) {
            const int col = wn * 64 + ni * 8 + lc;
            const float b0 = (col < 128) ? bS[col] : bN[col - 128];
            const float b1 = (col + 1 < 128) ? bS[col + 1] : bN[col - 127];
            d[mi][ni][0] = fmaxf(d[mi][ni][0] + b0, 0.f);
            d[mi][ni][1] = fmaxf(d[mi][ni][1] + b1, 0.f);
            d[mi][ni][2] = fmaxf(d[mi][ni][2] + b0, 0.f);
            d[mi][ni][3] = fmaxf(d[mi][ni][3] + b1, 0.f);
            s0 += d[mi][ni][0] * d[mi][ni][0] + d[mi][ni][1] * d[mi][ni][1];
            s1 += d[mi][ni][2] * d[mi][ni][2] + d[mi][ni][3] * d[mi][ni][3];
        }
        s0 += __shfl_xor_sync(0xffffffffu, s0, 1);
        s0 += __shfl_xor_sync(0xffffffffu, s0, 2);
        s1 += __shfl_xor_sync(0xffffffffu, s1, 1);
        s1 += __shfl_xor_sync(0xffffffffu, s1, 2);
        if ((lane & 3) == 0) {
            atomicAdd(&ss[r0], s0);
            atomicAdd(&ss[r0 + 8], s1);
        }
    }
    __syncthreads();

#pragma unroll
    for (int mi = 0; mi < 2; ++mi) {
        const int r0 = wm * 32 + mi * 16 + lr;
        const float sc0 = 1.0f / fmaxf(sqrtf(ss[r0]), 1e-12f);
        const float sc1 = 1.0f / fmaxf(sqrtf(ss[r0 + 8]), 1e-12f);
#pragma unroll
        for (int ni = 0; ni < 8; ++ni) {
            const int col = wn * 64 + ni * 8 + lc;
            uint32_t h, l;
            split2(d[mi][ni][0] * sc0, d[mi][ni][1] * sc0, h, l);
            *(uint32_t*)(smem + C_HH + (size_t)(r0 * RSH + col) * 2) = h;
            *(uint32_t*)(smem + C_HL + (size_t)(r0 * RSH + col) * 2) = l;
            split2(d[mi][ni][2] * sc1, d[mi][ni][3] * sc1, h, l);
            *(uint32_t*)(smem + C_HH + (size_t)((r0 + 8) * RSH + col) * 2) = h;
            *(uint32_t*)(smem + C_HL + (size_t)((r0 + 8) * RSH + col) * 2) = l;
        }
    }
    CP_WAIT0();
    __syncthreads();

    float e[2][4][4];
#pragma unroll
    for (int i = 0; i < 2; ++i)
#pragma unroll
        for (int j = 0; j < 4; ++j)
#pragma unroll
            for (int k = 0; k < 4; ++k) e[i][j][k] = 0.f;

#pragma unroll
    for (int ch = 0; ch < 4; ++ch) {
        const int kb = ch * 64;
        const uint32_t fH = sb + C_FC, fL = fH + 18432;
#pragma unroll
        for (int ks = 0; ks < 4; ++ks) {
            uint32_t ah[2][4], al[2][4];
#pragma unroll
            for (int mi = 0; mi < 2; ++mi) {
                uint32_t ad = (uint32_t)((wm * 32 + mi * 16 + aro) * RSH
                                         + kb + ks * 16 + aco) * 2;
                ldmx4(ah[mi], sb + C_HH + ad);
                ldmx4(al[mi], sb + C_HL + ad);
            }
#pragma unroll
            for (int nip = 0; nip < 2; ++nip) {
                uint32_t bd = (uint32_t)((wn * 32 + nip * 16 + bro) * RSA
                                         + ks * 16 + bco) * 2;
                uint32_t th[4], tl[4];
                ldmx4(th, fH + bd);
                ldmx4(tl, fL + bd);
#pragma unroll
                for (int sub = 0; sub < 2; ++sub) {
                    const int ni = 2 * nip + sub;
#pragma unroll
                    for (int mi = 0; mi < 2; ++mi) {
                        mma16816(e[mi][ni], ah[mi], th[2 * sub], th[2 * sub + 1]);
                        mma16816(e[mi][ni], ah[mi], tl[2 * sub], tl[2 * sub + 1]);
                        mma16816(e[mi][ni], al[mi], th[2 * sub], th[2 * sub + 1]);
                    }
                }
            }
        }
        if (ch < 3) {
            __syncthreads();
            ISSUE_FC(ch + 1);
            CP_COMMIT();
            CP_WAIT0();
            __syncthreads();
        }
    }

#pragma unroll
    for (int mi = 0; mi < 2; ++mi) {
        const int row = m0 + wm * 32 + mi * 16 + lr;
#pragma unroll
        for (int ni = 0; ni < 4; ++ni) {
            const int col = wn * 32 + ni * 8 + lc;
            const float b0 = __ldg(&fcb[col]), b1 = __ldg(&fcb[col + 1]);
            *(float2*)(out + (size_t)row * 128 + col) =
                make_float2(e[mi][ni][0] + b0, e[mi][ni][1] + b1);
            *(float2*)(out + (size_t)(row + 8) * 128 + col) =
                make_float2(e[mi][ni][2] + b0, e[mi][ni][3] + b1);
        }
    }
}

// ---------------------------------------------------------------------------
extern "C" void kernel_launch(void* const* d_in, const int* in_sizes, int n_in,
                              void* d_out, int out_size)
{
    const float* emb      = (const float*)d_in[0];
    const float* w_self0  = (const float*)d_in[1];
    const float* b_self0  = (const float*)d_in[2];
    const float* w_neigh0 = (const float*)d_in[3];
    const float* b_neigh0 = (const float*)d_in[4];
    const float* w_self1  = (const float*)d_in[5];
    const float* b_self1  = (const float*)d_in[6];
    const float* w_neigh1 = (const float*)d_in[7];
    const float* b_neigh1 = (const float*)d_in[8];
    const float* fc_w     = (const float*)d_in[9];
    const float* fc_b     = (const float*)d_in[10];
    const int*   nodeids  = (const int*)d_in[11];
    const int*   neigh1   = (const int*)d_in[12];
    const int*   neigh2   = (const int*)d_in[13];
    float*       out      = (float*)d_out;

    __nv_bfloat16 *WHI, *WLO;
    float *F0, *F1;
    cudaGetSymbolAddress((void**)&WHI, g_whi);
    cudaGetSymbolAddress((void**)&WLO, g_wlo);
    cudaGetSymbolAddress((void**)&F0, g_F0);
    cudaGetSymbolAddress((void**)&F1, g_F1);

    cudaFuncSetAttribute(layer0_k, cudaFuncAttributeMaxDynamicSharedMemorySize, G_SMEM);
    cudaFuncSetAttribute(l1fc_k,   cudaFuncAttributeMaxDynamicSharedMemorySize, L_SMEM);

    layer0_k<<<2048, 256, G_SMEM>>>(emb, nodeids, neigh1, neigh2,
                                    w_self0, w_neigh0, w_self1, w_neigh1, fc_w,
                                    WHI, WLO, WHI, WLO,
                                    b_self0, b_neigh0, F0, F1);

    l1fc_k<<<B_ROOT / 64, 256, L_SMEM>>>(F0, F1,
                                         WHI + 65536, WLO + 65536,
                                         b_self1, b_neigh1,
                                         WHI + 131072, WLO + 131072,
                                         fc_b, out);
}

// round 17
// speedup vs baseline: 1.3202x; 1.1251x over previous
#include <cuda_runtime.h>
#include <cuda_bf16.h>
#include <cstdint>

// ---------------------------------------------------------------------------
// GraphSAGE, mma.sync bf16 hi/lo (3-product fp32-accurate). Two launches:
// layer0_k: weight pre-split fused (8 converter CTAs + acquire flag); 4 GEMM
//   segments CONTIGUOUS; gemm_body = 256 thr, M64 x N128, K=256 in 4 chunks,
//   2 CTAs/SM. NEW: gather lanes 8-per-row (128B full-line spans per instr,
//   2 rows/thread) -> halved L1tex wavefronts vs the 64B-span map.
// l1fc_k: 256 thr, 2 CTAs/SM; stage1 M64 x N256 layer-1 (k32 chunks), row
//   L2-norm, stage2 FC — fused; coalesced interleaved loaders.
// ---------------------------------------------------------------------------

#define B_ROOT 16384
#define R1     49152
#define RSA    72            // k64 tile row stride (bf16 elems)
#define RSC    40            // k32 tile row stride (bf16 elems)
#define RSH    264           // h row stride

// layer0 smem (bytes)
#define GA(b)  ((b) * 18432)                 // A: hi +0, lo +9216
#define GW(b)  (36864 + (b) * 36864)         // W: hi +0, lo +18432
#define G_SMEM 110592
// l1fc smem (bytes)
#define C_ASH  0
#define C_ASL  5120
#define C_ANH  10240
#define C_ANL  15360
#define C_W(b) (20480 + (b) * 40960)
#define C_HH   0
#define C_HL   33792
#define C_FC   67584
#define C_SS   104448
#define L_SMEM 104704

// ---------------- scratch ----------------------------------------------------
__device__ float g_F0[B_ROOT * 256];
__device__ float g_F1[R1 * 256];
__device__ __nv_bfloat16 g_whi[5 * 32768];
__device__ __nv_bfloat16 g_wlo[5 * 32768];
__device__ unsigned g_wflag;

// ---------------- helpers ----------------------------------------------------
__device__ __forceinline__ uint32_t smem_u32(const void* p) {
    uint32_t a;
    asm("{ .reg .u64 t; cvta.to.shared.u64 t, %1; cvt.u32.u64 %0, t; }"
        : "=r"(a) : "l"(p));
    return a;
}
__device__ __forceinline__ void split2(float a, float b, uint32_t& h, uint32_t& l) {
    __nv_bfloat16 ah = __float2bfloat16_rn(a), bh = __float2bfloat16_rn(b);
    __nv_bfloat16 al = __float2bfloat16_rn(a - __bfloat162float(ah));
    __nv_bfloat16 bl = __float2bfloat16_rn(b - __bfloat162float(bh));
    __nv_bfloat162 ph = __halves2bfloat162(ah, bh);
    __nv_bfloat162 pl = __halves2bfloat162(al, bl);
    h = *reinterpret_cast<uint32_t*>(&ph);
    l = *reinterpret_cast<uint32_t*>(&pl);
}
__device__ __forceinline__ void mma16816(float* d, const uint32_t* a,
                                         uint32_t b0, uint32_t b1) {
    asm volatile(
        "mma.sync.aligned.m16n8k16.row.col.f32.bf16.bf16.f32 "
        "{%0,%1,%2,%3}, {%4,%5,%6,%7}, {%8,%9}, {%0,%1,%2,%3};"
        : "+f"(d[0]), "+f"(d[1]), "+f"(d[2]), "+f"(d[3])
        : "r"(a[0]), "r"(a[1]), "r"(a[2]), "r"(a[3]), "r"(b0), "r"(b1));
}
__device__ __forceinline__ void ldmx4(uint32_t* r, uint32_t a) {
    asm volatile("ldmatrix.sync.aligned.m8n8.x4.shared.b16 {%0,%1,%2,%3}, [%4];"
                 : "=r"(r[0]), "=r"(r[1]), "=r"(r[2]), "=r"(r[3]) : "r"(a));
}
__device__ __forceinline__ void cp16(uint32_t dst, const void* src) {
    asm volatile("cp.async.cg.shared.global [%0], [%1], 16;" :: "r"(dst), "l"(src));
}
#define CP_COMMIT() asm volatile("cp.async.commit_group;" ::: "memory")
#define CP_WAIT0()  asm volatile("cp.async.wait_group 0;"  ::: "memory")

// ---------------- layer-0 GEMM body (full-line gather spans) --------------------
// GATHER: 0 = A[idx[m]], 1 = mean_{j<KF} A[idx[m*KF+j]]
// Lane map: thread owns rows {rp, rp+1} (rp = (tid>>3)*2) and float4 slot q8 of
// each 8-slot group -> 8 lanes read 128B CONTIGUOUS (one full line) per row
// per instruction.
template <int GATHER, int KF>
__device__ __forceinline__ void
gemm_body(char* smem, const float* __restrict__ A, const int* __restrict__ idx,
          const __nv_bfloat16* __restrict__ w_hi, const __nv_bfloat16* __restrict__ w_lo,
          const float* __restrict__ bias,
          float* __restrict__ C, int ldc, int col_off, int m0)
{
    const uint32_t sb = smem_u32(smem);
    const int tid = threadIdx.x, lane = tid & 31, wid = tid >> 5;
    const int wm = wid >> 2, wn = wid & 3;
    const int lr = lane >> 2, lc = (lane & 3) * 2;
    const int g  = lane >> 3, lm = lane & 7;
    const int aro = ((g & 1) << 3) + lm, aco = (g >> 1) << 3;
    const int bro = ((g >> 1) << 3) + lm, bco = (g & 1) << 3;
    const int rp = (tid >> 3) * 2;    // rows rp, rp+1
    const int q8 = tid & 7;           // float4 slot within 8-slot group

    auto ISSUE_W = [&](int ch, int buf) {
        const int kb = ch * 64;
#pragma unroll
        for (int i = 0; i < 8; ++i) {
            int o = tid + i * 256;
            int plane = o >> 10, ix = o & 1023;
            int row = ix >> 3, c8 = (ix & 7) * 8;
            const __nv_bfloat16* src =
                (plane ? w_lo : w_hi) + (size_t)row * 256 + kb + c8;
            cp16(sb + GW(buf) + (plane ? 18432 : 0)
                 + (uint32_t)(row * RSA + c8) * 2, src);
        }
    };

    int rows[2][KF];
#pragma unroll
    for (int w = 0; w < 2; ++w) {
        if (GATHER == 0) rows[w][0] = idx[m0 + rp + w];
        else {
#pragma unroll
            for (int j = 0; j < KF; ++j)
                rows[w][j] = idx[(size_t)(m0 + rp + w) * KF + j];
        }
    }

    // v[w*8 + hh*4 + c]: row rp+w, slot group hh (slot q8 + 8*hh), float c
    float v[16];
    auto PREF = [&](int ch) {
        const int kb4 = ch * 16;
        if (GATHER == 0) {
            const float4* p0 = (const float4*)A + (size_t)rows[0][0] * 64 + kb4 + q8;
            const float4* p1 = (const float4*)A + (size_t)rows[1][0] * 64 + kb4 + q8;
            float4 t0 = __ldg(p0), t1 = __ldg(p0 + 8);
            float4 t2 = __ldg(p1), t3 = __ldg(p1 + 8);
            v[0]  = t0.x; v[1]  = t0.y; v[2]  = t0.z; v[3]  = t0.w;
            v[4]  = t1.x; v[5]  = t1.y; v[6]  = t1.z; v[7]  = t1.w;
            v[8]  = t2.x; v[9]  = t2.y; v[10] = t2.z; v[11] = t2.w;
            v[12] = t3.x; v[13] = t3.y; v[14] = t3.z; v[15] = t3.w;
        } else {
#pragma unroll
            for (int i = 0; i < 16; ++i) v[i] = 0.f;
#pragma unroll
            for (int w = 0; w < 2; ++w) {
                float4 t[2 * KF];               // independent loads -> high MLP
#pragma unroll
                for (int j = 0; j < KF; ++j) {
                    const float4* p = (const float4*)A
                        + (size_t)rows[w][j] * 64 + kb4 + q8;
                    t[j * 2]     = __ldg(p);      // slot group 0
                    t[j * 2 + 1] = __ldg(p + 8);  // slot group 1
                }
#pragma unroll
                for (int j = 0; j < KF; ++j)
#pragma unroll
                    for (int hh = 0; hh < 2; ++hh) {
                        const float4 f = t[j * 2 + hh];
                        const int o = w * 8 + hh * 4;
                        v[o + 0] += f.x; v[o + 1] += f.y;
                        v[o + 2] += f.z; v[o + 3] += f.w;
                    }
            }
        }
    };
    auto STORE = [&](int buf) {
        const float s = 1.0f / (float)KF;
        char* base = smem + GA(buf);
#pragma unroll
        for (int w = 0; w < 2; ++w)
#pragma unroll
            for (int hh = 0; hh < 2; ++hh) {
                const float* vv = v + w * 8 + hh * 4;
                uint32_t h0, l0, h1, l1;
                split2(vv[0] * s, vv[1] * s, h0, l0);
                split2(vv[2] * s, vv[3] * s, h1, l1);
                const size_t off = ((size_t)(rp + w) * RSA + (q8 + 8 * hh) * 4) * 2;
                *(uint2*)(base + off)        = make_uint2(h0, h1);
                *(uint2*)(base + 9216 + off) = make_uint2(l0, l1);
            }
    };

    float d[2][4][4];
#pragma unroll
    for (int i = 0; i < 2; ++i)
#pragma unroll
        for (int j = 0; j < 4; ++j)
#pragma unroll
            for (int k = 0; k < 4; ++k) d[i][j][k] = 0.f;

    ISSUE_W(0, 0);
    CP_COMMIT();
    PREF(0);
    STORE(0);
    CP_WAIT0();
    __syncthreads();

#pragma unroll
    for (int ch = 0; ch < 4; ++ch) {
        const int cb = ch & 1, nb = cb ^ 1;
        if (ch < 3) {
            ISSUE_W(ch + 1, nb);
            CP_COMMIT();
            PREF(ch + 1);
        }
        const uint32_t aH = sb + GA(cb), aL = aH + 9216;
        const uint32_t wH = sb + GW(cb), wL = wH + 18432;
#pragma unroll
        for (int ks = 0; ks < 4; ++ks) {
            uint32_t ah[2][4], al[2][4];
#pragma unroll
            for (int mi = 0; mi < 2; ++mi) {
                uint32_t ad = (uint32_t)((wm * 32 + mi * 16 + aro) * RSA
                                         + ks * 16 + aco) * 2;
                ldmx4(ah[mi], aH + ad);
                ldmx4(al[mi], aL + ad);
            }
            uint32_t bh[4][2], bl[4][2];
#pragma unroll
            for (int nip = 0; nip < 2; ++nip) {
                uint32_t bd = (uint32_t)((wn * 32 + nip * 16 + bro) * RSA
                                         + ks * 16 + bco) * 2;
                uint32_t t4[4];
                ldmx4(t4, wH + bd);
                bh[2 * nip][0] = t4[0]; bh[2 * nip][1] = t4[1];
                bh[2 * nip + 1][0] = t4[2]; bh[2 * nip + 1][1] = t4[3];
                ldmx4(t4, wL + bd);
                bl[2 * nip][0] = t4[0]; bl[2 * nip][1] = t4[1];
                bl[2 * nip + 1][0] = t4[2]; bl[2 * nip + 1][1] = t4[3];
            }
#pragma unroll
            for (int ni = 0; ni < 4; ++ni)
#pragma unroll
                for (int mi = 0; mi < 2; ++mi) {
                    mma16816(d[mi][ni], ah[mi], bh[ni][0], bh[ni][1]);
                    mma16816(d[mi][ni], ah[mi], bl[ni][0], bl[ni][1]);
                    mma16816(d[mi][ni], al[mi], bh[ni][0], bh[ni][1]);
                }
        }
        if (ch < 3) {
            STORE(nb);
            CP_WAIT0();
        }
        __syncthreads();
    }

#pragma unroll
    for (int mi = 0; mi < 2; ++mi) {
        const int row = m0 + wm * 32 + mi * 16 + lr;
#pragma unroll
        for (int ni = 0; ni < 4; ++ni) {
            const int col = wn * 32 + ni * 8 + lc;
            const float b0 = __ldg(&bias[col]), b1 = __ldg(&bias[col + 1]);
            *(float2*)(C + (size_t)row * ldc + col_off + col) =
                make_float2(fmaxf(d[mi][ni][0] + b0, 0.f),
                            fmaxf(d[mi][ni][1] + b1, 0.f));
            *(float2*)(C + (size_t)(row + 8) * ldc + col_off + col) =
                make_float2(fmaxf(d[mi][ni][2] + b0, 0.f),
                            fmaxf(d[mi][ni][3] + b1, 0.f));
        }
    }
}

// ---------------- layer 0: fused weight-split + contiguous segments --------------
__global__ void __launch_bounds__(256, 2)
layer0_k(const float* __restrict__ emb,
         const int* __restrict__ nodeids, const int* __restrict__ neigh1,
         const int* __restrict__ neigh2,
         const float* __restrict__ ws0, const float* __restrict__ wn0,
         const float* __restrict__ ws1, const float* __restrict__ wn1,
         const float* __restrict__ fcw,
         __nv_bfloat16* __restrict__ whi_o, __nv_bfloat16* __restrict__ wlo_o,
         const __nv_bfloat16* __restrict__ whi, const __nv_bfloat16* __restrict__ wlo,
         const float* __restrict__ bs0, const float* __restrict__ bn0,
         float* __restrict__ F0, float* __restrict__ F1)
{
    extern __shared__ char smem[];
    const int bid = blockIdx.x;
    const int tid = threadIdx.x;

    if (bid < 8) {
        const float* src[5] = {ws0, wn0, ws1, wn1, fcw};
#pragma unroll
        for (int i = 0; i < 20; ++i) {
            int idx4 = bid * 5120 + i * 256 + tid;
            int base = idx4 * 4;
            float4 f = __ldg((const float4*)(src[base >> 15] + (base & 32767)));
            uint32_t h0, l0, h1, l1;
            split2(f.x, f.y, h0, l0);
            split2(f.z, f.w, h1, l1);
            *(uint2*)(whi_o + base) = make_uint2(h0, h1);
            *(uint2*)(wlo_o + base) = make_uint2(l0, l1);
        }
        __syncthreads();
        if (tid == 0) {
            unsigned old;
            asm volatile("atom.add.release.gpu.u32 %0, [%1], 1;"
                         : "=r"(old) : "l"(&g_wflag) : "memory");
        }
    }
    if (tid == 0) {
        unsigned val;
        do {
            asm volatile("ld.acquire.gpu.u32 %0, [%1];"
                         : "=r"(val) : "l"(&g_wflag) : "memory");
            if (val >= 8u) break;
            __nanosleep(64);
        } while (true);
    }
    __syncthreads();

    if (bid < 768) {
        gemm_body<1, 5>(smem, emb, neigh2, whi + 32768, wlo + 32768, bn0,
                        F1, 256, 128, bid * 64);
    } else if (bid < 1536) {
        gemm_body<0, 1>(smem, emb, neigh1, whi, wlo, bs0,
                        F1, 256, 0, (bid - 768) * 64);
    } else if (bid < 1792) {
        gemm_body<1, 3>(smem, emb, neigh1, whi + 32768, wlo + 32768, bn0,
                        F0, 256, 128, (bid - 1536) * 64);
    } else {
        gemm_body<0, 1>(smem, emb, nodeids, whi, wlo, bs0,
                        F0, 256, 0, (bid - 1792) * 64);
    }
}

// ---------------- fused layer1 + L2-norm + FC, 256 thr, 2 CTAs/SM ----------------
__global__ void __launch_bounds__(256, 2)
l1fc_k(const float* __restrict__ F0, const float* __restrict__ F1,
       const __nv_bfloat16* __restrict__ w1_hi, const __nv_bfloat16* __restrict__ w1_lo,
       const float* __restrict__ bS, const float* __restrict__ bN,
       const __nv_bfloat16* __restrict__ fc_hi, const __nv_bfloat16* __restrict__ fc_lo,
       const float* __restrict__ fcb, float* __restrict__ out)
{
    extern __shared__ char smem[];
    const uint32_t sb = smem_u32(smem);
    const int tid = threadIdx.x, lane = tid & 31, wid = tid >> 5;
    const int wm = wid >> 2, wn = wid & 3;
    const int lr = lane >> 2, lc = (lane & 3) * 2;
    const int g  = lane >> 3, lm = lane & 7;
    const int aro = ((g & 1) << 3) + lm, aco = (g >> 1) << 3;
    const int bro = ((g >> 1) << 3) + lm, bco = (g & 1) << 3;
    const int m0 = blockIdx.x * 64;

    if (blockIdx.x == 0 && tid == 0) {
        asm volatile("st.relaxed.gpu.u32 [%0], 0;" :: "l"(&g_wflag) : "memory");
    }

    const bool isSelf = tid < 128;
    const int lt = tid & 127;
    const int r = lt >> 1, q2 = lt & 1;

    auto ISSUE_W = [&](int ch, int buf) {
        const int kb = ch * 32;
#pragma unroll
        for (int i = 0; i < 8; ++i) {
            int o = tid + i * 256;
            int plane = o >> 10, ix = o & 1023;
            int row = ix >> 2, c8 = (ix & 3) * 8;
            const __nv_bfloat16* src =
                (plane ? w1_lo : w1_hi) + (size_t)row * 256 + kb + c8;
            cp16(sb + C_W(buf) + (plane ? 20480 : 0)
                 + (uint32_t)(row * RSC + c8) * 2, src);
        }
    };

    float v[16];
    auto PREF = [&](int ch) {
        const int kb4 = ch * 8;
        if (isSelf) {
            const float4* p = (const float4*)F0 + (size_t)(m0 + r) * 64 + kb4 + q2;
            float4 t0 = __ldg(p), t1 = __ldg(p + 2), t2 = __ldg(p + 4), t3 = __ldg(p + 6);
            v[0]  = t0.x; v[1]  = t0.y; v[2]  = t0.z; v[3]  = t0.w;
            v[4]  = t1.x; v[5]  = t1.y; v[6]  = t1.z; v[7]  = t1.w;
            v[8]  = t2.x; v[9]  = t2.y; v[10] = t2.z; v[11] = t2.w;
            v[12] = t3.x; v[13] = t3.y; v[14] = t3.z; v[15] = t3.w;
        } else {
            float4 t[12];
#pragma unroll
            for (int j = 0; j < 3; ++j) {
                const float4* p = (const float4*)F1
                    + (size_t)((m0 + r) * 3 + j) * 64 + kb4 + q2;
                t[j * 4 + 0] = __ldg(p);
                t[j * 4 + 1] = __ldg(p + 2);
                t[j * 4 + 2] = __ldg(p + 4);
                t[j * 4 + 3] = __ldg(p + 6);
            }
#pragma unroll
            for (int i = 0; i < 16; ++i) v[i] = 0.f;
#pragma unroll
            for (int j = 0; j < 3; ++j)
#pragma unroll
                for (int q = 0; q < 4; ++q) {
                    const float4 f = t[j * 4 + q];
                    v[q * 4 + 0] += f.x; v[q * 4 + 1] += f.y;
                    v[q * 4 + 2] += f.z; v[q * 4 + 3] += f.w;
                }
#pragma unroll
            for (int i = 0; i < 16; ++i) v[i] *= (1.0f / 3.0f);
        }
    };
    auto STORE = [&]() {
        char* base = smem + (isSelf ? C_ASH : C_ANH);
#pragma unroll
        for (int q = 0; q < 4; ++q) {
            uint32_t h0, l0, h1, l1;
            split2(v[q * 4 + 0], v[q * 4 + 1], h0, l0);
            split2(v[q * 4 + 2], v[q * 4 + 3], h1, l1);
            const size_t off = ((size_t)r * RSC + (q2 + 2 * q) * 4) * 2;
            *(uint2*)(base + off)        = make_uint2(h0, h1);
            *(uint2*)(base + 5120 + off) = make_uint2(l0, l1);
        }
    };

    float d[2][8][4];
#pragma unroll
    for (int i = 0; i < 2; ++i)
#pragma unroll
        for (int j = 0; j < 8; ++j)
#pragma unroll
            for (int k = 0; k < 4; ++k) d[i][j][k] = 0.f;

    ISSUE_W(0, 0);
    CP_COMMIT();
    PREF(0);
    STORE();
    CP_WAIT0();
    __syncthreads();

#pragma unroll
    for (int ch = 0; ch < 8; ++ch) {
        const int cb = ch & 1, nb = cb ^ 1;
        if (ch < 7) {
            ISSUE_W(ch + 1, nb);
            CP_COMMIT();
            PREF(ch + 1);
        }
        const uint32_t aH = sb + (wn < 2 ? C_ASH : C_ANH);
        const uint32_t aL = aH + 5120;
        const uint32_t wH = sb + C_W(cb), wL = wH + 20480;
#pragma unroll
        for (int ks = 0; ks < 2; ++ks) {
            uint32_t ah[2][4], al[2][4];
#pragma unroll
            for (int mi = 0; mi < 2; ++mi) {
                uint32_t ad = (uint32_t)((wm * 32 + mi * 16 + aro) * RSC
                                         + ks * 16 + aco) * 2;
                ldmx4(ah[mi], aH + ad);
                ldmx4(al[mi], aL + ad);
            }
#pragma unroll
            for (int nip = 0; nip < 4; ++nip) {
                uint32_t bd = (uint32_t)((wn * 64 + nip * 16 + bro) * RSC
                                         + ks * 16 + bco) * 2;
                uint32_t th[4], tl[4];
                ldmx4(th, wH + bd);
                ldmx4(tl, wL + bd);
#pragma unroll
                for (int sub = 0; sub < 2; ++sub) {
                    const int ni = 2 * nip + sub;
#pragma unroll
                    for (int mi = 0; mi < 2; ++mi) {
                        mma16816(d[mi][ni], ah[mi], th[2 * sub], th[2 * sub + 1]);
                        mma16816(d[mi][ni], ah[mi], tl[2 * sub], tl[2 * sub + 1]);
                        mma16816(d[mi][ni], al[mi], th[2 * sub], th[2 * sub + 1]);
                    }
                }
            }
        }
        __syncthreads();
        if (ch < 7) {
            STORE();
            CP_WAIT0();
            __syncthreads();
        }
    }

    auto ISSUE_FC = [&](int ch) {
        const int kb = ch * 64;
#pragma unroll
        for (int i = 0; i < 8; ++i) {
            int o = tid + i * 256;
            int plane = o >> 10, ix = o & 1023;
            int row = ix >> 3, c8 = (ix & 7) * 8;
            const __nv_bfloat16* src = (plane ? fc_lo : fc_hi)
                                     + (size_t)row * 256 + kb + c8;
            cp16(sb + C_FC + (plane ? 18432 : 0)
                 + (uint32_t)(row * RSA + c8) * 2, src);
        }
    };
    ISSUE_FC(0);
    CP_COMMIT();

    float* ss = (float*)(smem + C_SS);
    if (tid < 64) ss[tid] = 0.f;
    __syncthreads();

#pragma unroll
    for (int mi = 0; mi < 2; ++mi) {
        const int r0 = wm * 32 + mi * 16 + lr;
        float s0 = 0.f, s1 = 0.f;
#pragma unroll
        for (int ni = 0; ni < 8; ++ni) {
            const int col = wn * 64 + ni * 8 + lc;
            const float b0 = (col < 128) ? bS[col] : bN[col - 128];
            const float b1 = (col + 1 < 128) ? bS[col + 1] : bN[col - 127];
            d[mi][ni][0] = fmaxf(d[mi][ni][0] + b0, 0.f);
            d[mi][ni][1] = fmaxf(d[mi][ni][1] + b1, 0.f);
            d[mi][ni][2] = fmaxf(d[mi][ni][2] + b0, 0.f);
            d[mi][ni][3] = fmaxf(d[mi][ni][3] + b1, 0.f);
            s0 += d[mi][ni][0] * d[mi][ni][0] + d[mi][ni][1] * d[mi][ni][1];
            s1 += d[mi][ni][2] * d[mi][ni][2] + d[mi][ni][3] * d[mi][ni][3];
        }
        s0 += __shfl_xor_sync(0xffffffffu, s0, 1);
        s0 += __shfl_xor_sync(0xffffffffu, s0, 2);
        s1 += __shfl_xor_sync(0xffffffffu, s1, 1);
        s1 += __shfl_xor_sync(0xffffffffu, s1, 2);
        if ((lane & 3) == 0) {
            atomicAdd(&ss[r0], s0);
            atomicAdd(&ss[r0 + 8], s1);
        }
    }
    __syncthreads();

#pragma unroll
    for (int mi = 0; mi < 2; ++mi) {
        const int r0 = wm * 32 + mi * 16 + lr;
        const float sc0 = 1.0f / fmaxf(sqrtf(ss[r0]), 1e-12f);
        const float sc1 = 1.0f / fmaxf(sqrtf(ss[r0 + 8]), 1e-12f);
#pragma unroll
        for (int ni = 0; ni < 8; ++ni) {
            const int col = wn * 64 + ni * 8 + lc;
            uint32_t h, l;
            split2(d[mi][ni][0] * sc0, d[mi][ni][1] * sc0, h, l);
            *(uint32_t*)(smem + C_HH + (size_t)(r0 * RSH + col) * 2) = h;
            *(uint32_t*)(smem + C_HL + (size_t)(r0 * RSH + col) * 2) = l;
            split2(d[mi][ni][2] * sc1, d[mi][ni][3] * sc1, h, l);
            *(uint32_t*)(smem + C_HH + (size_t)((r0 + 8) * RSH + col) * 2) = h;
            *(uint32_t*)(smem + C_HL + (size_t)((r0 + 8) * RSH + col) * 2) = l;
        }
    }
    CP_WAIT0();
    __syncthreads();

    float e[2][4][4];
#pragma unroll
    for (int i = 0; i < 2; ++i)
#pragma unroll
        for (int j = 0; j < 4; ++j)
#pragma unroll
            for (int k = 0; k < 4; ++k) e[i][j][k] = 0.f;

#pragma unroll
    for (int ch = 0; ch < 4; ++ch) {
        const int kb = ch * 64;
        const uint32_t fH = sb + C_FC, fL = fH + 18432;
#pragma unroll
        for (int ks = 0; ks < 4; ++ks) {
            uint32_t ah[2][4], al[2][4];
#pragma unroll
            for (int mi = 0; mi < 2; ++mi) {
                uint32_t ad = (uint32_t)((wm * 32 + mi * 16 + aro) * RSH
                                         + kb + ks * 16 + aco) * 2;
                ldmx4(ah[mi], sb + C_HH + ad);
                ldmx4(al[mi], sb + C_HL + ad);
            }
#pragma unroll
            for (int nip = 0; nip < 2; ++nip) {
                uint32_t bd = (uint32_t)((wn * 32 + nip * 16 + bro) * RSA
                                         + ks * 16 + bco) * 2;
                uint32_t th[4], tl[4];
                ldmx4(th, fH + bd);
                ldmx4(tl, fL + bd);
#pragma unroll
                for (int sub = 0; sub < 2; ++sub) {
                    const int ni = 2 * nip + sub;
#pragma unroll
                    for (int mi = 0; mi < 2; ++mi) {
                        mma16816(e[mi][ni], ah[mi], th[2 * sub], th[2 * sub + 1]);
                        mma16816(e[mi][ni], ah[mi], tl[2 * sub], tl[2 * sub + 1]);
                        mma16816(e[mi][ni], al[mi], th[2 * sub], th[2 * sub + 1]);
                    }
                }
            }
        }
        if (ch < 3) {
            __syncthreads();
            ISSUE_FC(ch + 1);
            CP_COMMIT();
            CP_WAIT0();
            __syncthreads();
        }
    }

#pragma unroll
    for (int mi = 0; mi < 2; ++mi) {
        const int row = m0 + wm * 32 + mi * 16 + lr;
#pragma unroll
        for (int ni = 0; ni < 4; ++ni) {
            const int col = wn * 32 + ni * 8 + lc;
            const float b0 = __ldg(&fcb[col]), b1 = __ldg(&fcb[col + 1]);
            *(float2*)(out + (size_t)row * 128 + col) =
                make_float2(e[mi][ni][0] + b0, e[mi][ni][1] + b1);
            *(float2*)(out + (size_t)(row + 8) * 128 + col) =
                make_float2(e[mi][ni][2] + b0, e[mi][ni][3] + b1);
        }
    }
}

// ---------------------------------------------------------------------------
extern "C" void kernel_launch(void* const* d_in, const int* in_sizes, int n_in,
                              void* d_out, int out_size)
{
    const float* emb      = (const float*)d_in[0];
    const float* w_self0  = (const float*)d_in[1];
    const float* b_self0  = (const float*)d_in[2];
    const float* w_neigh0 = (const float*)d_in[3];
    const float* b_neigh0 = (const float*)d_in[4];
    const float* w_self1  = (const float*)d_in[5];
    const float* b_self1  = (const float*)d_in[6];
    const float* w_neigh1 = (const float*)d_in[7];
    const float* b_neigh1 = (const float*)d_in[8];
    const float* fc_w     = (const float*)d_in[9];
    const float* fc_b     = (const float*)d_in[10];
    const int*   nodeids  = (const int*)d_in[11];
    const int*   neigh1   = (const int*)d_in[12];
    const int*   neigh2   = (const int*)d_in[13];
    float*       out      = (float*)d_out;

    __nv_bfloat16 *WHI, *WLO;
    float *F0, *F1;
    cudaGetSymbolAddress((void**)&WHI, g_whi);
    cudaGetSymbolAddress((void**)&WLO, g_wlo);
    cudaGetSymbolAddress((void**)&F0, g_F0);
    cudaGetSymbolAddress((void**)&F1, g_F1);

    cudaFuncSetAttribute(layer0_k, cudaFuncAttributeMaxDynamicSharedMemorySize, G_SMEM);
    cudaFuncSetAttribute(l1fc_k,   cudaFuncAttributeMaxDynamicSharedMemorySize, L_SMEM);

    layer0_k<<<2048, 256, G_SMEM>>>(emb, nodeids, neigh1, neigh2,
                                    w_self0, w_neigh0, w_self1, w_neigh1, fc_w,
                                    WHI, WLO, WHI, WLO,
                                    b_self0, b_neigh0, F0, F1);

    l1fc_k<<<B_ROOT / 64, 256, L_SMEM>>>(F0, F1,
                                         WHI + 65536, WLO + 65536,
                                         b_self1, b_neigh1,
                                         WHI + 131072, WLO + 131072,
                                         fc_b, out);
}